// round 3
// baseline (speedup 1.0000x reference)
#include <cuda_runtime.h>
#include <math.h>

// DPSR: scatter -> 3D rFFT -> spectral Poisson solve -> 3D irFFT -> gather/normalize
// Fused pipeline (3 FFT kernels instead of 6):
//   K1 k_fwdZY : per (bc,x) plane: z-FFT (R2C) + y-FFT.  ras -> d_sp
//   K2 k_specX : fwd x-FFT + spectral combine + mirror-DIT inverse x-FFT.
//                d_sp(3ch) -> d_inv1
//   K3 k_invYZ : per (b,x) plane: inverse y-FFT (mirror-DIT) + C2R z-FFT. -> d_phi
//
// Axis-order conventions:
//   - ky axis of d_sp/d_inv1 stored DIGIT-REVERSED: address a holds frequency
//     f = 4*bitrev5(a&31) + (a>>5).  Writers store lane t reg r at a=t+32r
//     (coalesced); K3 consumes it with the mirror-DIT inverse.
//   - z axis of d_phi stored digit-reversed the same way; gather/final compute
//     permuted addresses (their reads are scattered anyway / within 512B).
//   - kz axis natural (truncated to 0..64), x and y axes natural.

#define NRES 128
#define NKZ  65
#define VOL  (NRES*NRES*NRES)
#define NPTS 65536

__device__ float  d_ras[6*VOL];                 // [bc][x][y][z]
__device__ float2 d_sp[6*NRES*NKZ*NRES];        // [bc][x][kz][kya]
__device__ float2 d_inv1[2*NKZ*NRES*NRES];      // [b][kz][x][kya]
__device__ float  d_phi[2*VOL];                 // [b][x][y][za]
__device__ float  d_accum[2];

__device__ __forceinline__ float2 cmul(float2 a, float2 b) {
    return make_float2(a.x*b.x - a.y*b.y, a.x*b.y + a.y*b.x);
}
__device__ __forceinline__ float2 cadd(float2 a, float2 b) { return make_float2(a.x+b.x, a.y+b.y); }
__device__ __forceinline__ float2 csub(float2 a, float2 b) { return make_float2(a.x-b.x, a.y-b.y); }
__device__ __forceinline__ int bitrev5(int t) { return (int)(__brev((unsigned)t) >> 27); }
// digit-reversed address of spatial/freq index k in a 128-dim permuted axis
__device__ __forceinline__ int paddr(int k) { return bitrev5(k >> 2) + ((k & 3) << 5); }

// tw[j] = exp(sign * 2*pi*i * j / 128), 64 entries
__device__ __forceinline__ void build_tw64(float2* tw, int tid, float sign) {
    if (tid < 64) {
        float s, c;
        sincosf(sign * 6.28318530717958647f * (float)tid * (1.0f/128.0f), &s, &c);
        tw[tid] = make_float2(c, s);
    }
}

// Forward/inverse (natural input) warp FFT. Lane t holds v[r] = x[t+32r].
// Output: v[r] = X[4*bitrev5(t)+r]. DIR=0 fwd (tw sign -1), DIR=1 inv (tw sign +1).
template<int DIR>
__device__ __forceinline__ void warp_fft128(float2 v[4], const float2* __restrict__ tw, int t) {
    float2 t0 = cadd(v[0], v[2]);
    float2 t1 = csub(v[0], v[2]);
    float2 t2 = cadd(v[1], v[3]);
    float2 t3 = csub(v[1], v[3]);
    float2 t3r = DIR ? make_float2(-t3.y, t3.x) : make_float2(t3.y, -t3.x);
    v[0] = cadd(t0, t2);
    v[2] = csub(t0, t2);
    v[1] = cadd(t1, t3r);
    v[3] = csub(t1, t3r);
    float2 w1 = tw[t];
    float2 w2 = tw[2*t];
    v[1] = cmul(v[1], w1);
    v[2] = cmul(v[2], w2);
    v[3] = cmul(v[3], cmul(w1, w2));
#pragma unroll
    for (int d = 16; d >= 1; d >>= 1) {
        int m = (t & (d-1)) * (16/d);
        float2 w = tw[4*m];
        bool hi = (t & d) != 0;
        float s = hi ? -1.f : 1.f;
#pragma unroll
        for (int r = 0; r < 4; r++) {
            float2 p;
            p.x = __shfl_xor_sync(0xffffffffu, v[r].x, d);
            p.y = __shfl_xor_sync(0xffffffffu, v[r].y, d);
            float2 tmp = make_float2(p.x + s*v[r].x, p.y + s*v[r].y);
            v[r] = hi ? cmul(tmp, w) : tmp;
        }
    }
}

// Mirror-DIT inverse (unnormalized): consumes digit-reversed layout
// (lane t reg r = X[4*bitrev5(t)+r]) and produces natural v[r] = x[t+32r].
// twp must be built with sign=+1.
__device__ __forceinline__ void warp_ifft128_rev(float2 v[4], const float2* __restrict__ twp, int t) {
#pragma unroll
    for (int d = 1; d <= 16; d <<= 1) {
        int m = (t & (d-1)) * (16/d);
        float2 w = twp[4*m];
        bool hi = (t & d) != 0;
#pragma unroll
        for (int r = 0; r < 4; r++) {
            float2 u = hi ? cmul(v[r], w) : v[r];
            float2 p;
            p.x = __shfl_xor_sync(0xffffffffu, u.x, d);
            p.y = __shfl_xor_sync(0xffffffffu, u.y, d);
            v[r] = hi ? csub(p, u) : cadd(u, p);
        }
    }
    float2 w1 = twp[t], w2 = twp[2*t];
    v[1] = cmul(v[1], w1);
    v[2] = cmul(v[2], w2);
    v[3] = cmul(v[3], cmul(w1, w2));
    float2 t0 = cadd(v[0], v[2]), t1 = csub(v[0], v[2]);
    float2 t2 = cadd(v[1], v[3]), t3 = csub(v[1], v[3]);
    float2 t3r = make_float2(-t3.y, t3.x);
    v[0] = cadd(t0, t2);
    v[1] = cadd(t1, t3r);
    v[2] = csub(t0, t2);
    v[3] = csub(t1, t3r);
}

// ---------------------------------------------------------------- zero scratch
__global__ void k_zero() {
    int i = blockIdx.x * blockDim.x + threadIdx.x;
    float4* p = (float4*)d_ras;
    int n4 = 6*VOL/4;
    for (int k = i; k < n4; k += gridDim.x * blockDim.x)
        p[k] = make_float4(0.f, 0.f, 0.f, 0.f);
    if (i < 2) d_accum[i] = 0.f;
}

// ---------------------------------------------------------------- scatter
__global__ void k_scatter(const float* __restrict__ V, const float* __restrict__ N) {
    int id = blockIdx.x * blockDim.x + threadIdx.x;
    if (id >= 2*NPTS) return;
    int b = id >> 16;
    float px = V[3*id+0]*128.f, py = V[3*id+1]*128.f, pz = V[3*id+2]*128.f;
    int ix0 = max(0, min(127, (int)floorf(px)));
    int iy0 = max(0, min(127, (int)floorf(py)));
    int iz0 = max(0, min(127, (int)floorf(pz)));
    float fx = px - (float)ix0, fy = py - (float)iy0, fz = pz - (float)iz0;
    int ix[2] = {ix0, (ix0+1)&127};
    int iy[2] = {iy0, (iy0+1)&127};
    int iz[2] = {iz0, (iz0+1)&127};
    float wx[2] = {1.f-fx, fx}, wy[2] = {1.f-fy, fy}, wz[2] = {1.f-fz, fz};
    float nx = N[3*id+0], ny = N[3*id+1], nz = N[3*id+2];
    float* r = d_ras + (size_t)b*3*VOL;
#pragma unroll
    for (int cx = 0; cx < 2; cx++)
#pragma unroll
        for (int cy = 0; cy < 2; cy++)
#pragma unroll
            for (int cz = 0; cz < 2; cz++) {
                int sp = (ix[cx]*NRES + iy[cy])*NRES + iz[cz];
                float w = wx[cx]*wy[cy]*wz[cz];
                atomicAdd(r + sp,          w*nx);
                atomicAdd(r + VOL + sp,    w*ny);
                atomicAdd(r + 2*VOL + sp,  w*nz);
            }
}

// ------------------------------------------ K1: fused forward z (R2C) + y FFT
// One block per (bc,x) plane. Dyn smem: float2 plane[128][65] (stride 65).
__global__ void __launch_bounds__(512) k_fwdZY() {
    extern __shared__ float2 sh[];              // 128*65 float2
    __shared__ float2 tw[64];
    int tid = threadIdx.x, w = tid >> 5, t = tid & 31;
    build_tw64(tw, tid, -1.f);
    __syncthreads();
    int x = blockIdx.x, bc = blockIdx.y;
    const float* base = d_ras + (size_t)(bc*NRES + x) * NRES * NRES;
    int u = bitrev5(t);
    // stage 1: 128 z-lines (R2C, keep kz<=64)
    for (int j = 0; j < 8; j++) {
        int y = w + 16*j;
        const float* in = base + y*NRES;
        float2 v[4];
#pragma unroll
        for (int r = 0; r < 4; r++) v[r] = make_float2(in[t + 32*r], 0.f);
        warp_fft128<0>(v, tw, t);
#pragma unroll
        for (int r = 0; r < 4; r++) {
            int kz = 4*u + r;
            if (kz <= 64) sh[y*NKZ + kz] = v[r];
        }
    }
    __syncthreads();
    // stage 2: 65 y-lines, write permuted-ky coalesced
    float2* dstp = d_sp + (size_t)(bc*NRES + x) * NKZ * NRES;
    for (int kz = w; kz < NKZ; kz += 16) {
        float2 v[4];
#pragma unroll
        for (int r = 0; r < 4; r++) v[r] = sh[(t + 32*r)*NKZ + kz];
        warp_fft128<0>(v, tw, t);
        float2* dst = dstp + kz*NRES;
#pragma unroll
        for (int r = 0; r < 4; r++) dst[t + 32*r] = v[r];   // address = t+32r (perm ky)
    }
}

// ------------- K2: forward x-FFT + spectral combine + mirror-DIT inverse x-FFT
// Block = (kya-tile c, kz, b). 32 warps; warp l handles kya = 32c+l.
__global__ void __launch_bounds__(1024) k_specX() {
    __shared__ float2 tile[128*33];
    __shared__ float2 twf[64];
    __shared__ float2 twi[64];
    int tid = threadIdx.x, l = tid >> 5, t = tid & 31;
    build_tw64(twf, tid, -1.f);
    if (tid >= 64 && tid < 128) build_tw64(twi, tid - 64, 1.f);
    int c = blockIdx.x, kz = blockIdx.y, b = blockIdx.z;
    int kya0 = 32*c;
    int fyi = 4*bitrev5(l) + c;                 // true ky frequency of this line
    float fy = (fyi < 64) ? (float)fyi : (float)(fyi - 128);
    float fz = (float)kz;
    int u = bitrev5(t);
    const float TWOPI = 6.28318530717958647f;
    float2 acc[4];
#pragma unroll
    for (int r = 0; r < 4; r++) acc[r] = make_float2(0.f, 0.f);
    for (int ch = 0; ch < 3; ch++) {
        __syncthreads();                        // tile reuse barrier (also covers tw build)
        const float2* src = d_sp + ((size_t)(b*3 + ch)*NRES*NKZ + kz)*NRES + kya0;
        for (int i = tid; i < 4096; i += 1024) {
            int xx = i >> 5, kyl = i & 31;
            tile[xx*33 + kyl] = src[(size_t)xx*NKZ*NRES + kyl];
        }
        __syncthreads();
        float2 v[4];
#pragma unroll
        for (int r = 0; r < 4; r++) v[r] = tile[(t + 32*r)*33 + l];
        warp_fft128<0>(v, twf, t);
#pragma unroll
        for (int r = 0; r < 4; r++) {
            int kx = 4*u + r;
            float wgt;
            if (ch == 0)      wgt = TWOPI * (float)(kx < 64 ? kx : kx - 128);
            else if (ch == 1) wgt = TWOPI * fy;
            else              wgt = TWOPI * fz;
            acc[r].x += wgt * v[r].x;
            acc[r].y += wgt * v[r].y;
        }
    }
    float2 P[4];
#pragma unroll
    for (int r = 0; r < 4; r++) {
        int kx = 4*u + r;
        float fx = (float)(kx < 64 ? kx : kx - 128);
        float d2 = fx*fx + fy*fy + fz*fz;
        float G = expf(-0.01220703125f * d2);            // 0.5*(sig*2/128)^2
        float L = -39.478417604357434f * d2 + 1e-6f;     // -4*pi^2*|f|^2 + eps
        P[r] = make_float2(G*acc[r].y/L, -G*acc[r].x/L); // -i*G*acc/L
        if (kx == 0 && fyi == 0 && kz == 0) P[r] = make_float2(0.f, 0.f);
    }
    warp_ifft128_rev(P, twi, t);                // -> natural x
    __syncthreads();
#pragma unroll
    for (int r = 0; r < 4; r++) tile[(t + 32*r)*33 + l] = P[r];
    __syncthreads();
    float2* dst = d_inv1 + (size_t)(b*NKZ + kz)*NRES*NRES + kya0;
    for (int i = tid; i < 4096; i += 1024) {
        int xx = i >> 5, kyl = i & 31;
        dst[(size_t)xx*NRES + kyl] = tile[xx*33 + kyl];
    }
}

// --------------- K3: fused inverse y-FFT (mirror-DIT) + inverse z (C2R)
// One block per (b,x). Dyn smem: float2 plane[128 y][65 kz] stride 65.
__global__ void __launch_bounds__(512) k_invYZ() {
    extern __shared__ float2 sh[];              // 128*65 float2
    __shared__ float2 twi[64];
    int tid = threadIdx.x, w = tid >> 5, t = tid & 31;
    build_tw64(twi, tid, 1.f);
    __syncthreads();
    int x = blockIdx.x, b = blockIdx.y;
    // stage 1: 65 ky-lines (permuted-ky input -> natural y out)
    for (int kz = w; kz < NKZ; kz += 16) {
        const float2* in = d_inv1 + ((size_t)(b*NKZ + kz)*NRES + x)*NRES;
        float2 v[4];
#pragma unroll
        for (int r = 0; r < 4; r++) v[r] = in[t + 32*r];
        warp_ifft128_rev(v, twi, t);            // natural y = t+32r
#pragma unroll
        for (int r = 0; r < 4; r++) sh[(t + 32*r)*NKZ + kz] = v[r];
    }
    __syncthreads();
    // stage 2: 128 C2R z-lines, write permuted-z coalesced
    const float sc = 1.0f / 2097152.0f;         // 1/128^3
    float* outb = d_phi + (size_t)(b*NRES + x) * NRES * NRES;
    for (int j = 0; j < 8; j++) {
        int y = w + 16*j;
        const float2* row = sh + y*NKZ;
        float2 v[4];
        v[0] = row[t];
        v[1] = row[t + 32];
        v[2] = row[64 - t];  v[2].y = -v[2].y;  // Hermitian extension
        v[3] = row[32 - t];  v[3].y = -v[3].y;
        warp_fft128<1>(v, twi, t);
        float* o = outb + y*NRES;
#pragma unroll
        for (int r = 0; r < 4; r++) o[t + 32*r] = v[r].x * sc;  // perm z addr
    }
}

// ---------------------------------------------------------------- gather + mean
__global__ void k_gather(const float* __restrict__ V) {
    __shared__ float red[256];
    int id = blockIdx.x * 256 + threadIdx.x;    // 131072; b uniform per block
    int b = id >> 16;
    float px = V[3*id+0]*128.f, py = V[3*id+1]*128.f, pz = V[3*id+2]*128.f;
    int ix0 = max(0, min(127, (int)floorf(px)));
    int iy0 = max(0, min(127, (int)floorf(py)));
    int iz0 = max(0, min(127, (int)floorf(pz)));
    float fx = px - (float)ix0, fy = py - (float)iy0, fz = pz - (float)iz0;
    int ix[2] = {ix0, (ix0+1)&127};
    int iy[2] = {iy0, (iy0+1)&127};
    int az[2] = {paddr(iz0), paddr((iz0+1)&127)};     // permuted z addresses
    float wx[2] = {1.f-fx, fx}, wy[2] = {1.f-fy, fy}, wz[2] = {1.f-fz, fz};
    const float* ph = d_phi + (size_t)b*VOL;
    float fv = 0.f;
#pragma unroll
    for (int cx = 0; cx < 2; cx++)
#pragma unroll
        for (int cy = 0; cy < 2; cy++)
#pragma unroll
            for (int cz = 0; cz < 2; cz++)
                fv += wx[cx]*wy[cy]*wz[cz] * ph[(ix[cx]*NRES + iy[cy])*NRES + az[cz]];
    red[threadIdx.x] = fv;
    __syncthreads();
    for (int s = 128; s > 0; s >>= 1) {
        if (threadIdx.x < s) red[threadIdx.x] += red[threadIdx.x + s];
        __syncthreads();
    }
    if (threadIdx.x == 0) atomicAdd(&d_accum[b], red[0]);
}

// ---------------------------------------------------------------- finalize
__global__ void k_final(float* __restrict__ out) {
    int id = blockIdx.x * 256 + threadIdx.x;    // 4194304 total
    int b = id >> 21;
    int z = id & 127;
    int base = id - z;
    float off  = d_accum[b] * (1.0f/65536.0f);
    float p000 = d_phi[(size_t)b * VOL];        // paddr(0)=0
    float s = 0.5f / fabsf(p000 - off);
    out[id] = -(d_phi[base + paddr(z)] - off) * s;
}

// ---------------------------------------------------------------- launch
extern "C" void kernel_launch(void* const* d_in, const int* in_sizes, int n_in,
                              void* d_out, int out_size) {
    const float* V = (const float*)d_in[0];
    const float* N = (const float*)d_in[1];
    float* out = (float*)d_out;

    const int planeBytes = NRES*NKZ*sizeof(float2);   // 66560
    cudaFuncSetAttribute(k_fwdZY, cudaFuncAttributeMaxDynamicSharedMemorySize, planeBytes);
    cudaFuncSetAttribute(k_invYZ, cudaFuncAttributeMaxDynamicSharedMemorySize, planeBytes);

    k_zero<<<4096, 256>>>();
    k_scatter<<<512, 256>>>(V, N);
    k_fwdZY<<<dim3(128, 6), 512, planeBytes>>>();     // 768 planes
    k_specX<<<dim3(4, 65, 2), 1024>>>();              // 520 line-tiles
    k_invYZ<<<dim3(128, 2), 512, planeBytes>>>();     // 256 planes
    k_gather<<<512, 256>>>(V);
    k_final<<<16384, 256>>>(out);
}

// round 4
// speedup vs baseline: 1.0759x; 1.0759x over previous
#include <cuda_runtime.h>
#include <math.h>

// DPSR: scatter -> 3D rFFT -> spectral Poisson solve -> 3D irFFT -> gather/normalize
// Fused pipeline (3 FFT kernels):
//   K1 k_fwdZY : per (bc,x) plane: z-FFT (R2C) + y-FFT.  ras -> d_sp
//   K2 k_specX : fwd x-FFT + spectral combine + mirror-DIT inverse x-FFT.
//                All 3 channels staged to smem in ONE load phase (high MLP),
//                512-thread blocks (2 blocks/SM). d_sp(3ch) -> d_inv1
//   K3 k_invYZ : per (b,x) plane: inverse y-FFT (mirror-DIT) + C2R z-FFT. -> d_phi
//
// Axis conventions:
//   - ky axis of d_sp/d_inv1 stored DIGIT-REVERSED: address a holds frequency
//     f = 4*bitrev5(a&31) + (a>>5). Writers store lane t reg r at a=t+32r
//     (coalesced); consumers use the mirror-DIT inverse.
//   - z axis of d_phi digit-reversed the same way; gather/final permute addresses.
//   - kz truncated natural (0..64); x, y natural.

#define NRES 128
#define NKZ  65
#define VOL  (NRES*NRES*NRES)
#define NPTS 65536
#define K2L  16          // kya lines per K2 block
#define K2TS (128*17)    // padded tile size (float2) per channel

__device__ float  d_ras[6*VOL];                 // [bc][x][y][z]
__device__ float2 d_sp[6*NRES*NKZ*NRES];        // [bc][x][kz][kya]
__device__ float2 d_inv1[2*NKZ*NRES*NRES];      // [b][kz][x][kya]
__device__ float  d_phi[2*VOL];                 // [b][x][y][za]
__device__ float  d_accum[2];

__device__ __forceinline__ float2 cmul(float2 a, float2 b) {
    return make_float2(a.x*b.x - a.y*b.y, a.x*b.y + a.y*b.x);
}
__device__ __forceinline__ float2 cadd(float2 a, float2 b) { return make_float2(a.x+b.x, a.y+b.y); }
__device__ __forceinline__ float2 csub(float2 a, float2 b) { return make_float2(a.x-b.x, a.y-b.y); }
__device__ __forceinline__ int bitrev5(int t) { return (int)(__brev((unsigned)t) >> 27); }
__device__ __forceinline__ int paddr(int k) { return bitrev5(k >> 2) + ((k & 3) << 5); }

__device__ __forceinline__ void build_tw64(float2* tw, int tid, float sign) {
    if (tid < 64) {
        float s, c;
        sincosf(sign * 6.28318530717958647f * (float)tid * (1.0f/128.0f), &s, &c);
        tw[tid] = make_float2(c, s);
    }
}

// Natural-input warp FFT. Lane t holds v[r]=x[t+32r]; out v[r]=X[4*bitrev5(t)+r].
template<int DIR>
__device__ __forceinline__ void warp_fft128(float2 v[4], const float2* __restrict__ tw, int t) {
    float2 t0 = cadd(v[0], v[2]);
    float2 t1 = csub(v[0], v[2]);
    float2 t2 = cadd(v[1], v[3]);
    float2 t3 = csub(v[1], v[3]);
    float2 t3r = DIR ? make_float2(-t3.y, t3.x) : make_float2(t3.y, -t3.x);
    v[0] = cadd(t0, t2);
    v[2] = csub(t0, t2);
    v[1] = cadd(t1, t3r);
    v[3] = csub(t1, t3r);
    float2 w1 = tw[t], w2 = tw[2*t];
    v[1] = cmul(v[1], w1);
    v[2] = cmul(v[2], w2);
    v[3] = cmul(v[3], cmul(w1, w2));
#pragma unroll
    for (int d = 16; d >= 1; d >>= 1) {
        int m = (t & (d-1)) * (16/d);
        float2 w = tw[4*m];
        bool hi = (t & d) != 0;
        float s = hi ? -1.f : 1.f;
#pragma unroll
        for (int r = 0; r < 4; r++) {
            float2 p;
            p.x = __shfl_xor_sync(0xffffffffu, v[r].x, d);
            p.y = __shfl_xor_sync(0xffffffffu, v[r].y, d);
            float2 tmp = make_float2(p.x + s*v[r].x, p.y + s*v[r].y);
            v[r] = hi ? cmul(tmp, w) : tmp;
        }
    }
}

// Mirror-DIT inverse: consumes digit-reversed layout (lane t reg r = X[4*bitrev5(t)+r]),
// produces natural v[r]=x[t+32r]. twp built with sign=+1. Unnormalized.
__device__ __forceinline__ void warp_ifft128_rev(float2 v[4], const float2* __restrict__ twp, int t) {
#pragma unroll
    for (int d = 1; d <= 16; d <<= 1) {
        int m = (t & (d-1)) * (16/d);
        float2 w = twp[4*m];
        bool hi = (t & d) != 0;
#pragma unroll
        for (int r = 0; r < 4; r++) {
            float2 u = hi ? cmul(v[r], w) : v[r];
            float2 p;
            p.x = __shfl_xor_sync(0xffffffffu, u.x, d);
            p.y = __shfl_xor_sync(0xffffffffu, u.y, d);
            v[r] = hi ? csub(p, u) : cadd(u, p);
        }
    }
    float2 w1 = twp[t], w2 = twp[2*t];
    v[1] = cmul(v[1], w1);
    v[2] = cmul(v[2], w2);
    v[3] = cmul(v[3], cmul(w1, w2));
    float2 t0 = cadd(v[0], v[2]), t1 = csub(v[0], v[2]);
    float2 t2 = cadd(v[1], v[3]), t3 = csub(v[1], v[3]);
    float2 t3r = make_float2(-t3.y, t3.x);
    v[0] = cadd(t0, t2);
    v[1] = cadd(t1, t3r);
    v[2] = csub(t0, t2);
    v[3] = csub(t1, t3r);
}

// ---------------------------------------------------------------- zero scratch
__global__ void k_zero() {
    int i = blockIdx.x * blockDim.x + threadIdx.x;
    float4* p = (float4*)d_ras;
    int n4 = 6*VOL/4;
    for (int k = i; k < n4; k += gridDim.x * blockDim.x)
        p[k] = make_float4(0.f, 0.f, 0.f, 0.f);
    if (i < 2) d_accum[i] = 0.f;
}

// ---------------------------------------------------------------- scatter
__global__ void k_scatter(const float* __restrict__ V, const float* __restrict__ N) {
    int id = blockIdx.x * blockDim.x + threadIdx.x;
    if (id >= 2*NPTS) return;
    int b = id >> 16;
    float px = V[3*id+0]*128.f, py = V[3*id+1]*128.f, pz = V[3*id+2]*128.f;
    int ix0 = max(0, min(127, (int)floorf(px)));
    int iy0 = max(0, min(127, (int)floorf(py)));
    int iz0 = max(0, min(127, (int)floorf(pz)));
    float fx = px - (float)ix0, fy = py - (float)iy0, fz = pz - (float)iz0;
    int ix[2] = {ix0, (ix0+1)&127};
    int iy[2] = {iy0, (iy0+1)&127};
    int iz[2] = {iz0, (iz0+1)&127};
    float wx[2] = {1.f-fx, fx}, wy[2] = {1.f-fy, fy}, wz[2] = {1.f-fz, fz};
    float nx = N[3*id+0], ny = N[3*id+1], nz = N[3*id+2];
    float* r = d_ras + (size_t)b*3*VOL;
#pragma unroll
    for (int cx = 0; cx < 2; cx++)
#pragma unroll
        for (int cy = 0; cy < 2; cy++)
#pragma unroll
            for (int cz = 0; cz < 2; cz++) {
                int sp = (ix[cx]*NRES + iy[cy])*NRES + iz[cz];
                float w = wx[cx]*wy[cy]*wz[cz];
                atomicAdd(r + sp,          w*nx);
                atomicAdd(r + VOL + sp,    w*ny);
                atomicAdd(r + 2*VOL + sp,  w*nz);
            }
}

// ------------------------------------------ K1: fused forward z (R2C) + y FFT
__global__ void __launch_bounds__(512) k_fwdZY() {
    extern __shared__ float2 sh[];              // 128*65 float2
    __shared__ float2 tw[64];
    int tid = threadIdx.x, w = tid >> 5, t = tid & 31;
    build_tw64(tw, tid, -1.f);
    __syncthreads();
    int x = blockIdx.x, bc = blockIdx.y;
    const float* base = d_ras + (size_t)(bc*NRES + x) * NRES * NRES;
    int u = bitrev5(t);
    for (int j = 0; j < 8; j++) {
        int y = w + 16*j;
        const float* in = base + y*NRES;
        float2 v[4];
#pragma unroll
        for (int r = 0; r < 4; r++) v[r] = make_float2(in[t + 32*r], 0.f);
        warp_fft128<0>(v, tw, t);
#pragma unroll
        for (int r = 0; r < 4; r++) {
            int kz = 4*u + r;
            if (kz <= 64) sh[y*NKZ + kz] = v[r];
        }
    }
    __syncthreads();
    float2* dstp = d_sp + (size_t)(bc*NRES + x) * NKZ * NRES;
    for (int kz = w; kz < NKZ; kz += 16) {
        float2 v[4];
#pragma unroll
        for (int r = 0; r < 4; r++) v[r] = sh[(t + 32*r)*NKZ + kz];
        warp_fft128<0>(v, tw, t);
        float2* dst = dstp + kz*NRES;
#pragma unroll
        for (int r = 0; r < 4; r++) dst[t + 32*r] = v[r];   // permuted ky, coalesced
    }
}

// ------------- K2: forward x-FFT + spectral combine + mirror-DIT inverse x-FFT
// 512 threads = 16 warps; warp l handles kya = kya0 + l. Single staged load of
// all 3 channels into dyn smem -> one barrier -> barrier-free FFT phase.
__global__ void __launch_bounds__(512) k_specX() {
    extern __shared__ float2 tile[];            // 3 * K2TS float2 (51 KB)
    __shared__ float2 twf[64];
    __shared__ float2 twi[64];
    int tid = threadIdx.x, l = tid >> 5, t = tid & 31;
    build_tw64(twf, tid, -1.f);
    if (tid >= 64 && tid < 128) build_tw64(twi, tid - 64, 1.f);
    int c = blockIdx.x, kz = blockIdx.y, b = blockIdx.z;
    int kya0 = K2L*c;
    // ---- single load phase: 3 channels, 12 independent loads per thread
#pragma unroll
    for (int ch = 0; ch < 3; ch++) {
        const float2* src = d_sp + ((size_t)(b*3 + ch)*NRES*NKZ + kz)*NRES + kya0;
        float2* tch = tile + ch*K2TS;
        for (int i = tid; i < 128*K2L; i += 512) {
            int xx = i >> 4, kyl = i & 15;
            tch[xx*17 + kyl] = src[(size_t)xx*NKZ*NRES + kyl];
        }
    }
    __syncthreads();
    int kya = kya0 + l;
    int fyi = 4*bitrev5(kya & 31) + (kya >> 5);     // true ky frequency
    float fy = (fyi < 64) ? (float)fyi : (float)(fyi - 128);
    float fz = (float)kz;
    int u = bitrev5(t);
    const float TWOPI = 6.28318530717958647f;
    float2 acc[4];
#pragma unroll
    for (int r = 0; r < 4; r++) acc[r] = make_float2(0.f, 0.f);
#pragma unroll
    for (int ch = 0; ch < 3; ch++) {
        const float2* tch = tile + ch*K2TS;
        float2 v[4];
#pragma unroll
        for (int r = 0; r < 4; r++) v[r] = tch[(t + 32*r)*17 + l];
        warp_fft128<0>(v, twf, t);
#pragma unroll
        for (int r = 0; r < 4; r++) {
            int kx = 4*u + r;
            float wgt;
            if (ch == 0)      wgt = TWOPI * (float)(kx < 64 ? kx : kx - 128);
            else if (ch == 1) wgt = TWOPI * fy;
            else              wgt = TWOPI * fz;
            acc[r].x += wgt * v[r].x;
            acc[r].y += wgt * v[r].y;
        }
    }
    float2 P[4];
#pragma unroll
    for (int r = 0; r < 4; r++) {
        int kx = 4*u + r;
        float fx = (float)(kx < 64 ? kx : kx - 128);
        float d2 = fx*fx + fy*fy + fz*fz;
        float G = expf(-0.01220703125f * d2);            // 0.5*(sig*2/128)^2
        float L = -39.478417604357434f * d2 + 1e-6f;     // -4*pi^2*|f|^2 + eps
        P[r] = make_float2(G*acc[r].y/L, -G*acc[r].x/L); // -i*G*acc/L
        if (kx == 0 && fyi == 0 && kz == 0) P[r] = make_float2(0.f, 0.f);
    }
    warp_ifft128_rev(P, twi, t);                // -> natural x order
    __syncthreads();
#pragma unroll
    for (int r = 0; r < 4; r++) tile[(t + 32*r)*17 + l] = P[r];
    __syncthreads();
    float2* dst = d_inv1 + (size_t)(b*NKZ + kz)*NRES*NRES + kya0;
    for (int i = tid; i < 128*K2L; i += 512) {
        int xx = i >> 4, kyl = i & 15;
        dst[(size_t)xx*NRES + kyl] = tile[xx*17 + kyl];
    }
}

// --------------- K3: fused inverse y-FFT (mirror-DIT) + inverse z (C2R)
__global__ void __launch_bounds__(512) k_invYZ() {
    extern __shared__ float2 sh[];              // 128*65 float2
    __shared__ float2 twi[64];
    int tid = threadIdx.x, w = tid >> 5, t = tid & 31;
    build_tw64(twi, tid, 1.f);
    __syncthreads();
    int x = blockIdx.x, b = blockIdx.y;
    for (int kz = w; kz < NKZ; kz += 16) {
        const float2* in = d_inv1 + ((size_t)(b*NKZ + kz)*NRES + x)*NRES;
        float2 v[4];
#pragma unroll
        for (int r = 0; r < 4; r++) v[r] = in[t + 32*r];
        warp_ifft128_rev(v, twi, t);            // natural y = t+32r
#pragma unroll
        for (int r = 0; r < 4; r++) sh[(t + 32*r)*NKZ + kz] = v[r];
    }
    __syncthreads();
    const float sc = 1.0f / 2097152.0f;         // 1/128^3
    float* outb = d_phi + (size_t)(b*NRES + x) * NRES * NRES;
    for (int j = 0; j < 8; j++) {
        int y = w + 16*j;
        const float2* row = sh + y*NKZ;
        float2 v[4];
        v[0] = row[t];
        v[1] = row[t + 32];
        v[2] = row[64 - t];  v[2].y = -v[2].y;  // Hermitian extension
        v[3] = row[32 - t];  v[3].y = -v[3].y;
        warp_fft128<1>(v, twi, t);
        float* o = outb + y*NRES;
#pragma unroll
        for (int r = 0; r < 4; r++) o[t + 32*r] = v[r].x * sc;  // permuted z
    }
}

// ---------------------------------------------------------------- gather + mean
__global__ void k_gather(const float* __restrict__ V) {
    __shared__ float red[256];
    int id = blockIdx.x * 256 + threadIdx.x;    // 131072; b uniform per block
    int b = id >> 16;
    float px = V[3*id+0]*128.f, py = V[3*id+1]*128.f, pz = V[3*id+2]*128.f;
    int ix0 = max(0, min(127, (int)floorf(px)));
    int iy0 = max(0, min(127, (int)floorf(py)));
    int iz0 = max(0, min(127, (int)floorf(pz)));
    float fx = px - (float)ix0, fy = py - (float)iy0, fz = pz - (float)iz0;
    int ix[2] = {ix0, (ix0+1)&127};
    int iy[2] = {iy0, (iy0+1)&127};
    int az[2] = {paddr(iz0), paddr((iz0+1)&127)};
    float wx[2] = {1.f-fx, fx}, wy[2] = {1.f-fy, fy}, wz[2] = {1.f-fz, fz};
    const float* ph = d_phi + (size_t)b*VOL;
    float fv = 0.f;
#pragma unroll
    for (int cx = 0; cx < 2; cx++)
#pragma unroll
        for (int cy = 0; cy < 2; cy++)
#pragma unroll
            for (int cz = 0; cz < 2; cz++)
                fv += wx[cx]*wy[cy]*wz[cz] * ph[(ix[cx]*NRES + iy[cy])*NRES + az[cz]];
    red[threadIdx.x] = fv;
    __syncthreads();
    for (int s = 128; s > 0; s >>= 1) {
        if (threadIdx.x < s) red[threadIdx.x] += red[threadIdx.x + s];
        __syncthreads();
    }
    if (threadIdx.x == 0) atomicAdd(&d_accum[b], red[0]);
}

// ---------------------------------------------------------------- finalize
__global__ void k_final(float* __restrict__ out) {
    int id = blockIdx.x * 256 + threadIdx.x;    // 4194304 total
    int b = id >> 21;
    int z = id & 127;
    int base = id - z;
    float off  = d_accum[b] * (1.0f/65536.0f);
    float p000 = d_phi[(size_t)b * VOL];        // paddr(0)=0
    float s = 0.5f / fabsf(p000 - off);
    out[id] = -(d_phi[base + paddr(z)] - off) * s;
}

// ---------------------------------------------------------------- launch
extern "C" void kernel_launch(void* const* d_in, const int* in_sizes, int n_in,
                              void* d_out, int out_size) {
    const float* V = (const float*)d_in[0];
    const float* N = (const float*)d_in[1];
    float* out = (float*)d_out;

    const int planeBytes = NRES*NKZ*sizeof(float2);   // 66560
    const int k2Bytes    = 3*K2TS*sizeof(float2);     // 52224
    cudaFuncSetAttribute(k_fwdZY, cudaFuncAttributeMaxDynamicSharedMemorySize, planeBytes);
    cudaFuncSetAttribute(k_invYZ, cudaFuncAttributeMaxDynamicSharedMemorySize, planeBytes);
    cudaFuncSetAttribute(k_specX, cudaFuncAttributeMaxDynamicSharedMemorySize, k2Bytes);

    k_zero<<<4096, 256>>>();
    k_scatter<<<512, 256>>>(V, N);
    k_fwdZY<<<dim3(128, 6), 512, planeBytes>>>();     // 768 planes
    k_specX<<<dim3(8, 65, 2), 512, k2Bytes>>>();      // 1040 tiles of 16 lines
    k_invYZ<<<dim3(128, 2), 512, planeBytes>>>();     // 256 planes
    k_gather<<<512, 256>>>(V);
    k_final<<<16384, 256>>>(out);
}

// round 5
// speedup vs baseline: 1.1510x; 1.0698x over previous
#include <cuda_runtime.h>
#include <math.h>

// DPSR: scatter -> 3D rFFT -> spectral Poisson solve -> 3D irFFT -> gather/normalize
// Fused pipeline (3 FFT kernels):
//   K1 k_fwdZY : per (bc,x) plane: z-FFT (R2C) + y-FFT.  ras -> d_sp
//   K2 k_specX : channels 1,2 pre-combined with (2pi*fy, 2pi*fz) at load (FFT
//                linearity) -> 2 paired forward x-FFTs + combine + mirror-DIT
//                inverse x-FFT. d_sp(3ch) -> d_inv1
//   K3 k_invYZ : per (b,x) plane: inverse y-FFT (mirror-DIT) + C2R z-FFT. -> d_phi
//
// Axis conventions:
//   - ky axis of d_sp/d_inv1 DIGIT-REVERSED: address a holds freq
//     f = 4*bitrev5(a&31) + (a>>5). Writers store lane t reg r at a=t+32r.
//   - z axis of d_phi digit-reversed the same way; gather/final permute addresses.
//   - kz truncated natural (0..64); x, y natural.

#define NRES 128
#define NKZ  65
#define VOL  (NRES*NRES*NRES)
#define NPTS 65536
#define K2L  16          // kya lines per K2 block
#define K2TS (128*17)    // padded tile size (float2) per channel

__device__ float  d_ras[6*VOL];                 // [bc][x][y][z]
__device__ float2 d_sp[6*NRES*NKZ*NRES];        // [bc][x][kz][kya]
__device__ float2 d_inv1[2*NKZ*NRES*NRES];      // [b][kz][x][kya]
__device__ float  d_phi[2*VOL];                 // [b][x][y][za]
__device__ float  d_accum[2];

__device__ __forceinline__ float2 cmul(float2 a, float2 b) {
    return make_float2(a.x*b.x - a.y*b.y, a.x*b.y + a.y*b.x);
}
__device__ __forceinline__ float2 cadd(float2 a, float2 b) { return make_float2(a.x+b.x, a.y+b.y); }
__device__ __forceinline__ float2 csub(float2 a, float2 b) { return make_float2(a.x-b.x, a.y-b.y); }
__device__ __forceinline__ int bitrev5(int t) { return (int)(__brev((unsigned)t) >> 27); }
__device__ __forceinline__ int paddr(int k) { return bitrev5(k >> 2) + ((k & 3) << 5); }

__device__ __forceinline__ void build_tw64(float2* tw, int tid, float sign) {
    if (tid < 64) {
        float s, c;
        sincosf(sign * 6.28318530717958647f * (float)tid * (1.0f/128.0f), &s, &c);
        tw[tid] = make_float2(c, s);
    }
}

// Natural-input warp FFT. Lane t holds v[r]=x[t+32r]; out v[r]=X[4*bitrev5(t)+r].
template<int DIR>
__device__ __forceinline__ void warp_fft128(float2 v[4], const float2* __restrict__ tw, int t) {
    float2 t0 = cadd(v[0], v[2]);
    float2 t1 = csub(v[0], v[2]);
    float2 t2 = cadd(v[1], v[3]);
    float2 t3 = csub(v[1], v[3]);
    float2 t3r = DIR ? make_float2(-t3.y, t3.x) : make_float2(t3.y, -t3.x);
    v[0] = cadd(t0, t2);
    v[2] = csub(t0, t2);
    v[1] = cadd(t1, t3r);
    v[3] = csub(t1, t3r);
    float2 w1 = tw[t], w2 = tw[2*t];
    v[1] = cmul(v[1], w1);
    v[2] = cmul(v[2], w2);
    v[3] = cmul(v[3], cmul(w1, w2));
#pragma unroll
    for (int d = 16; d >= 1; d >>= 1) {
        int m = (t & (d-1)) * (16/d);
        float2 w = tw[4*m];
        bool hi = (t & d) != 0;
        float s = hi ? -1.f : 1.f;
#pragma unroll
        for (int r = 0; r < 4; r++) {
            float2 p;
            p.x = __shfl_xor_sync(0xffffffffu, v[r].x, d);
            p.y = __shfl_xor_sync(0xffffffffu, v[r].y, d);
            float2 tmp = make_float2(p.x + s*v[r].x, p.y + s*v[r].y);
            v[r] = hi ? cmul(tmp, w) : tmp;
        }
    }
}

// Radix-4 + twiddle prelude (first part of warp_fft128), for the paired variant.
template<int DIR>
__device__ __forceinline__ void fft_prelude(float2 v[4], const float2* __restrict__ tw, int t) {
    float2 t0 = cadd(v[0], v[2]);
    float2 t1 = csub(v[0], v[2]);
    float2 t2 = cadd(v[1], v[3]);
    float2 t3 = csub(v[1], v[3]);
    float2 t3r = DIR ? make_float2(-t3.y, t3.x) : make_float2(t3.y, -t3.x);
    v[0] = cadd(t0, t2);
    v[2] = csub(t0, t2);
    v[1] = cadd(t1, t3r);
    v[3] = csub(t1, t3r);
    float2 w1 = tw[t], w2 = tw[2*t];
    v[1] = cmul(v[1], w1);
    v[2] = cmul(v[2], w2);
    v[3] = cmul(v[3], cmul(w1, w2));
}

// Paired forward FFT: two independent 128-pt FFTs interleaved for ILP across
// the shfl dependency chains. Same in/out conventions as warp_fft128.
template<int DIR>
__device__ __forceinline__ void warp_fft128_x2(float2 va[4], float2 vb[4],
                                               const float2* __restrict__ tw, int t) {
    fft_prelude<DIR>(va, tw, t);
    fft_prelude<DIR>(vb, tw, t);
#pragma unroll
    for (int d = 16; d >= 1; d >>= 1) {
        int m = (t & (d-1)) * (16/d);
        float2 w = tw[4*m];
        bool hi = (t & d) != 0;
        float s = hi ? -1.f : 1.f;
#pragma unroll
        for (int r = 0; r < 4; r++) {
            float2 pa, pb;
            pa.x = __shfl_xor_sync(0xffffffffu, va[r].x, d);
            pa.y = __shfl_xor_sync(0xffffffffu, va[r].y, d);
            pb.x = __shfl_xor_sync(0xffffffffu, vb[r].x, d);
            pb.y = __shfl_xor_sync(0xffffffffu, vb[r].y, d);
            float2 ta = make_float2(pa.x + s*va[r].x, pa.y + s*va[r].y);
            float2 tb = make_float2(pb.x + s*vb[r].x, pb.y + s*vb[r].y);
            va[r] = hi ? cmul(ta, w) : ta;
            vb[r] = hi ? cmul(tb, w) : tb;
        }
    }
}

// Mirror-DIT inverse: consumes digit-reversed layout (lane t reg r = X[4*bitrev5(t)+r]),
// produces natural v[r]=x[t+32r]. twp built with sign=+1. Unnormalized.
__device__ __forceinline__ void warp_ifft128_rev(float2 v[4], const float2* __restrict__ twp, int t) {
#pragma unroll
    for (int d = 1; d <= 16; d <<= 1) {
        int m = (t & (d-1)) * (16/d);
        float2 w = twp[4*m];
        bool hi = (t & d) != 0;
#pragma unroll
        for (int r = 0; r < 4; r++) {
            float2 u = hi ? cmul(v[r], w) : v[r];
            float2 p;
            p.x = __shfl_xor_sync(0xffffffffu, u.x, d);
            p.y = __shfl_xor_sync(0xffffffffu, u.y, d);
            v[r] = hi ? csub(p, u) : cadd(u, p);
        }
    }
    float2 w1 = twp[t], w2 = twp[2*t];
    v[1] = cmul(v[1], w1);
    v[2] = cmul(v[2], w2);
    v[3] = cmul(v[3], cmul(w1, w2));
    float2 t0 = cadd(v[0], v[2]), t1 = csub(v[0], v[2]);
    float2 t2 = cadd(v[1], v[3]), t3 = csub(v[1], v[3]);
    float2 t3r = make_float2(-t3.y, t3.x);
    v[0] = cadd(t0, t2);
    v[1] = cadd(t1, t3r);
    v[2] = csub(t0, t2);
    v[3] = csub(t1, t3r);
}

// ---------------------------------------------------------------- zero scratch
__global__ void k_zero() {
    int i = blockIdx.x * blockDim.x + threadIdx.x;
    float4* p = (float4*)d_ras;
    int n4 = 6*VOL/4;
    for (int k = i; k < n4; k += gridDim.x * blockDim.x)
        p[k] = make_float4(0.f, 0.f, 0.f, 0.f);
    if (i < 2) d_accum[i] = 0.f;
}

// ---------------------------------------------------------------- scatter
__global__ void k_scatter(const float* __restrict__ V, const float* __restrict__ N) {
    int id = blockIdx.x * blockDim.x + threadIdx.x;
    if (id >= 2*NPTS) return;
    int b = id >> 16;
    float px = V[3*id+0]*128.f, py = V[3*id+1]*128.f, pz = V[3*id+2]*128.f;
    int ix0 = max(0, min(127, (int)floorf(px)));
    int iy0 = max(0, min(127, (int)floorf(py)));
    int iz0 = max(0, min(127, (int)floorf(pz)));
    float fx = px - (float)ix0, fy = py - (float)iy0, fz = pz - (float)iz0;
    int ix[2] = {ix0, (ix0+1)&127};
    int iy[2] = {iy0, (iy0+1)&127};
    int iz[2] = {iz0, (iz0+1)&127};
    float wx[2] = {1.f-fx, fx}, wy[2] = {1.f-fy, fy}, wz[2] = {1.f-fz, fz};
    float nx = N[3*id+0], ny = N[3*id+1], nz = N[3*id+2];
    float* r = d_ras + (size_t)b*3*VOL;
#pragma unroll
    for (int cx = 0; cx < 2; cx++)
#pragma unroll
        for (int cy = 0; cy < 2; cy++)
#pragma unroll
            for (int cz = 0; cz < 2; cz++) {
                int sp = (ix[cx]*NRES + iy[cy])*NRES + iz[cz];
                float w = wx[cx]*wy[cy]*wz[cz];
                atomicAdd(r + sp,          w*nx);
                atomicAdd(r + VOL + sp,    w*ny);
                atomicAdd(r + 2*VOL + sp,  w*nz);
            }
}

// ------------------------------------------ K1: fused forward z (R2C) + y FFT
__global__ void __launch_bounds__(512) k_fwdZY() {
    extern __shared__ float2 sh[];              // 128*65 float2
    __shared__ float2 tw[64];
    int tid = threadIdx.x, w = tid >> 5, t = tid & 31;
    build_tw64(tw, tid, -1.f);
    __syncthreads();
    int x = blockIdx.x, bc = blockIdx.y;
    const float* base = d_ras + (size_t)(bc*NRES + x) * NRES * NRES;
    int u = bitrev5(t);
    for (int j = 0; j < 8; j++) {
        int y = w + 16*j;
        const float* in = base + y*NRES;
        float2 v[4];
#pragma unroll
        for (int r = 0; r < 4; r++) v[r] = make_float2(in[t + 32*r], 0.f);
        warp_fft128<0>(v, tw, t);
#pragma unroll
        for (int r = 0; r < 4; r++) {
            int kz = 4*u + r;
            if (kz <= 64) sh[y*NKZ + kz] = v[r];
        }
    }
    __syncthreads();
    float2* dstp = d_sp + (size_t)(bc*NRES + x) * NKZ * NRES;
    for (int kz = w; kz < NKZ; kz += 16) {
        float2 v[4];
#pragma unroll
        for (int r = 0; r < 4; r++) v[r] = sh[(t + 32*r)*NKZ + kz];
        warp_fft128<0>(v, tw, t);
        float2* dst = dstp + kz*NRES;
#pragma unroll
        for (int r = 0; r < 4; r++) dst[t + 32*r] = v[r];   // permuted ky, coalesced
    }
}

// ------------- K2: paired fwd x-FFTs + spectral combine + mirror-DIT inverse
// Load phase pre-combines channels 1,2 (weights 2pi*fy, 2pi*fz are constant
// along x -> FFT linearity). 2 tiles in smem, one barrier, ILP-paired FFTs.
__global__ void __launch_bounds__(512, 2) k_specX() {
    extern __shared__ float2 tile[];            // 2 * K2TS float2 (~35 KB)
    __shared__ float2 twf[64];
    __shared__ float2 twi[64];
    int tid = threadIdx.x, l = tid >> 5, t = tid & 31;
    build_tw64(twf, tid, -1.f);
    if (tid >= 64 && tid < 128) build_tw64(twi, tid - 64, 1.f);
    int c = blockIdx.x, kz = blockIdx.y, b = blockIdx.z;
    int kya0 = K2L*c;
    const float TWOPI = 6.28318530717958647f;
    float fz = (float)kz;
    float2* tileX  = tile;
    float2* tileYZ = tile + K2TS;
    // ---- load phase: ch0 raw; ch1,ch2 combined with line weights
    {
        const float2* src0 = d_sp + ((size_t)(b*3 + 0)*NRES*NKZ + kz)*NRES + kya0;
        const float2* src1 = src0 + (size_t)NRES*NKZ*NRES;
        const float2* src2 = src1 + (size_t)NRES*NKZ*NRES;
        for (int i = tid; i < 128*K2L; i += 512) {
            int xx = i >> 4, kyl = i & 15;
            int kya = kya0 + kyl;
            int fyi = 4*bitrev5(kya & 31) + (kya >> 5);
            float fy = (fyi < 64) ? (float)fyi : (float)(fyi - 128);
            size_t off = (size_t)xx*NKZ*NRES + kyl;
            float2 e1 = src1[off];
            float2 e2 = src2[off];
            tileX[xx*17 + kyl] = src0[off];
            tileYZ[xx*17 + kyl] = make_float2(TWOPI*(fy*e1.x + fz*e2.x),
                                              TWOPI*(fy*e1.y + fz*e2.y));
        }
    }
    __syncthreads();
    int kya = kya0 + l;
    int fyi = 4*bitrev5(kya & 31) + (kya >> 5);     // true ky frequency
    float fy = (fyi < 64) ? (float)fyi : (float)(fyi - 128);
    int u = bitrev5(t);
    float2 vX[4], vYZ[4];
#pragma unroll
    for (int r = 0; r < 4; r++) {
        vX[r]  = tileX[(t + 32*r)*17 + l];
        vYZ[r] = tileYZ[(t + 32*r)*17 + l];
    }
    warp_fft128_x2<0>(vX, vYZ, twf, t);
    float2 P[4];
#pragma unroll
    for (int r = 0; r < 4; r++) {
        int kx = 4*u + r;
        float fx = (float)(kx < 64 ? kx : kx - 128);
        float wx = TWOPI * fx;
        float2 acc = make_float2(wx*vX[r].x + vYZ[r].x, wx*vX[r].y + vYZ[r].y);
        float d2 = fx*fx + fy*fy + fz*fz;
        float G = expf(-0.01220703125f * d2);            // 0.5*(sig*2/128)^2
        float L = -39.478417604357434f * d2 + 1e-6f;     // -4*pi^2*|f|^2 + eps
        P[r] = make_float2(G*acc.y/L, -G*acc.x/L);       // -i*G*acc/L
        if (kx == 0 && fyi == 0 && kz == 0) P[r] = make_float2(0.f, 0.f);
    }
    warp_ifft128_rev(P, twi, t);                // -> natural x order
    __syncthreads();
#pragma unroll
    for (int r = 0; r < 4; r++) tileX[(t + 32*r)*17 + l] = P[r];
    __syncthreads();
    float2* dst = d_inv1 + (size_t)(b*NKZ + kz)*NRES*NRES + kya0;
    for (int i = tid; i < 128*K2L; i += 512) {
        int xx = i >> 4, kyl = i & 15;
        dst[(size_t)xx*NRES + kyl] = tileX[xx*17 + kyl];
    }
}

// --------------- K3: fused inverse y-FFT (mirror-DIT) + inverse z (C2R)
__global__ void __launch_bounds__(512) k_invYZ() {
    extern __shared__ float2 sh[];              // 128*65 float2
    __shared__ float2 twi[64];
    int tid = threadIdx.x, w = tid >> 5, t = tid & 31;
    build_tw64(twi, tid, 1.f);
    __syncthreads();
    int x = blockIdx.x, b = blockIdx.y;
    for (int kz = w; kz < NKZ; kz += 16) {
        const float2* in = d_inv1 + ((size_t)(b*NKZ + kz)*NRES + x)*NRES;
        float2 v[4];
#pragma unroll
        for (int r = 0; r < 4; r++) v[r] = in[t + 32*r];
        warp_ifft128_rev(v, twi, t);            // natural y = t+32r
#pragma unroll
        for (int r = 0; r < 4; r++) sh[(t + 32*r)*NKZ + kz] = v[r];
    }
    __syncthreads();
    const float sc = 1.0f / 2097152.0f;         // 1/128^3
    float* outb = d_phi + (size_t)(b*NRES + x) * NRES * NRES;
    for (int j = 0; j < 8; j++) {
        int y = w + 16*j;
        const float2* row = sh + y*NKZ;
        float2 v[4];
        v[0] = row[t];
        v[1] = row[t + 32];
        v[2] = row[64 - t];  v[2].y = -v[2].y;  // Hermitian extension
        v[3] = row[32 - t];  v[3].y = -v[3].y;
        warp_fft128<1>(v, twi, t);
        float* o = outb + y*NRES;
#pragma unroll
        for (int r = 0; r < 4; r++) o[t + 32*r] = v[r].x * sc;  // permuted z
    }
}

// ---------------------------------------------------------------- gather + mean
__global__ void k_gather(const float* __restrict__ V) {
    __shared__ float red[256];
    int id = blockIdx.x * 256 + threadIdx.x;    // 131072; b uniform per block
    int b = id >> 16;
    float px = V[3*id+0]*128.f, py = V[3*id+1]*128.f, pz = V[3*id+2]*128.f;
    int ix0 = max(0, min(127, (int)floorf(px)));
    int iy0 = max(0, min(127, (int)floorf(py)));
    int iz0 = max(0, min(127, (int)floorf(pz)));
    float fx = px - (float)ix0, fy = py - (float)iy0, fz = pz - (float)iz0;
    int ix[2] = {ix0, (ix0+1)&127};
    int iy[2] = {iy0, (iy0+1)&127};
    int az[2] = {paddr(iz0), paddr((iz0+1)&127)};
    float wx[2] = {1.f-fx, fx}, wy[2] = {1.f-fy, fy}, wz[2] = {1.f-fz, fz};
    const float* ph = d_phi + (size_t)b*VOL;
    float fv = 0.f;
#pragma unroll
    for (int cx = 0; cx < 2; cx++)
#pragma unroll
        for (int cy = 0; cy < 2; cy++)
#pragma unroll
            for (int cz = 0; cz < 2; cz++)
                fv += wx[cx]*wy[cy]*wz[cz] * ph[(ix[cx]*NRES + iy[cy])*NRES + az[cz]];
    red[threadIdx.x] = fv;
    __syncthreads();
    for (int s = 128; s > 0; s >>= 1) {
        if (threadIdx.x < s) red[threadIdx.x] += red[threadIdx.x + s];
        __syncthreads();
    }
    if (threadIdx.x == 0) atomicAdd(&d_accum[b], red[0]);
}

// ---------------------------------------------------------------- finalize
__global__ void k_final(float* __restrict__ out) {
    int id = blockIdx.x * 256 + threadIdx.x;    // 4194304 total
    int b = id >> 21;
    int z = id & 127;
    int base = id - z;
    float off  = d_accum[b] * (1.0f/65536.0f);
    float p000 = d_phi[(size_t)b * VOL];        // paddr(0)=0
    float s = 0.5f / fabsf(p000 - off);
    out[id] = -(d_phi[base + paddr(z)] - off) * s;
}

// ---------------------------------------------------------------- launch
extern "C" void kernel_launch(void* const* d_in, const int* in_sizes, int n_in,
                              void* d_out, int out_size) {
    const float* V = (const float*)d_in[0];
    const float* N = (const float*)d_in[1];
    float* out = (float*)d_out;

    const int planeBytes = NRES*NKZ*sizeof(float2);   // 66560
    const int k2Bytes    = 2*K2TS*sizeof(float2);     // 34816
    cudaFuncSetAttribute(k_fwdZY, cudaFuncAttributeMaxDynamicSharedMemorySize, planeBytes);
    cudaFuncSetAttribute(k_invYZ, cudaFuncAttributeMaxDynamicSharedMemorySize, planeBytes);
    cudaFuncSetAttribute(k_specX, cudaFuncAttributeMaxDynamicSharedMemorySize, k2Bytes);

    k_zero<<<4096, 256>>>();
    k_scatter<<<512, 256>>>(V, N);
    k_fwdZY<<<dim3(128, 6), 512, planeBytes>>>();     // 768 planes
    k_specX<<<dim3(8, 65, 2), 512, k2Bytes>>>();      // 1040 tiles of 16 lines
    k_invYZ<<<dim3(128, 2), 512, planeBytes>>>();     // 256 planes
    k_gather<<<512, 256>>>(V);
    k_final<<<16384, 256>>>(out);
}

// round 6
// speedup vs baseline: 1.3379x; 1.1624x over previous
#include <cuda_runtime.h>
#include <math.h>

// DPSR: scatter -> 3D rFFT -> spectral Poisson solve -> 3D irFFT -> gather/normalize
// Fused pipeline (3 FFT kernels):
//   K1 k_fwdZY : per (bc,x) plane: packed-pair real z-FFTs (64 complex FFTs for
//                128 real lines) + Hermitian split on load + y-FFT. ras -> d_sp
//   K2 k_specX : channels 1,2 pre-combined with (2pi*fy, 2pi*fz) at load ->
//                paired forward x-FFTs + combine + mirror-DIT inverse. -> d_inv1
//   K3 k_invYZ : per (b,x) plane: inverse y-FFT (mirror-DIT) + packed-pair C2R
//                z-FFTs (64 complex FFTs emit 128 real lines). -> d_phi
//
// Axis conventions:
//   - ky axis of d_sp/d_inv1 DIGIT-REVERSED: address a holds freq
//     f = 4*bitrev5(a&31) + (a>>5). Writers store lane t reg r at a=t+32r.
//   - z axis of d_phi digit-reversed the same way; gather/final permute addresses.
//   - kz truncated natural (0..64); x, y natural.

#define NRES 128
#define NKZ  65
#define VOL  (NRES*NRES*NRES)
#define NPTS 65536
#define K2L  16          // kya lines per K2 block
#define K2TS (128*17)    // padded tile size (float2) per channel
#define K1PD 129         // K1 stage-1 smem row stride (float2), odd

__device__ float  d_ras[6*VOL];                 // [bc][x][y][z]
__device__ float2 d_sp[6*NRES*NKZ*NRES];        // [bc][x][kz][kya]
__device__ float2 d_inv1[2*NKZ*NRES*NRES];      // [b][kz][x][kya]
__device__ float  d_phi[2*VOL];                 // [b][x][y][za]
__device__ float  d_accum[2];

__device__ __forceinline__ float2 cmul(float2 a, float2 b) {
    return make_float2(a.x*b.x - a.y*b.y, a.x*b.y + a.y*b.x);
}
__device__ __forceinline__ float2 cadd(float2 a, float2 b) { return make_float2(a.x+b.x, a.y+b.y); }
__device__ __forceinline__ float2 csub(float2 a, float2 b) { return make_float2(a.x-b.x, a.y-b.y); }
__device__ __forceinline__ int bitrev5(int t) { return (int)(__brev((unsigned)t) >> 27); }
__device__ __forceinline__ int paddr(int k) { return bitrev5(k >> 2) + ((k & 3) << 5); }

__device__ __forceinline__ void build_tw64(float2* tw, int tid, float sign) {
    if (tid < 64) {
        float s, c;
        sincosf(sign * 6.28318530717958647f * (float)tid * (1.0f/128.0f), &s, &c);
        tw[tid] = make_float2(c, s);
    }
}

// Natural-input warp FFT. Lane t holds v[r]=x[t+32r]; out v[r]=X[4*bitrev5(t)+r].
template<int DIR>
__device__ __forceinline__ void warp_fft128(float2 v[4], const float2* __restrict__ tw, int t) {
    float2 t0 = cadd(v[0], v[2]);
    float2 t1 = csub(v[0], v[2]);
    float2 t2 = cadd(v[1], v[3]);
    float2 t3 = csub(v[1], v[3]);
    float2 t3r = DIR ? make_float2(-t3.y, t3.x) : make_float2(t3.y, -t3.x);
    v[0] = cadd(t0, t2);
    v[2] = csub(t0, t2);
    v[1] = cadd(t1, t3r);
    v[3] = csub(t1, t3r);
    float2 w1 = tw[t], w2 = tw[2*t];
    v[1] = cmul(v[1], w1);
    v[2] = cmul(v[2], w2);
    v[3] = cmul(v[3], cmul(w1, w2));
#pragma unroll
    for (int d = 16; d >= 1; d >>= 1) {
        int m = (t & (d-1)) * (16/d);
        float2 w = tw[4*m];
        bool hi = (t & d) != 0;
        float s = hi ? -1.f : 1.f;
#pragma unroll
        for (int r = 0; r < 4; r++) {
            float2 p;
            p.x = __shfl_xor_sync(0xffffffffu, v[r].x, d);
            p.y = __shfl_xor_sync(0xffffffffu, v[r].y, d);
            float2 tmp = make_float2(p.x + s*v[r].x, p.y + s*v[r].y);
            v[r] = hi ? cmul(tmp, w) : tmp;
        }
    }
}

// Radix-4 + twiddle prelude, for the paired variant.
template<int DIR>
__device__ __forceinline__ void fft_prelude(float2 v[4], const float2* __restrict__ tw, int t) {
    float2 t0 = cadd(v[0], v[2]);
    float2 t1 = csub(v[0], v[2]);
    float2 t2 = cadd(v[1], v[3]);
    float2 t3 = csub(v[1], v[3]);
    float2 t3r = DIR ? make_float2(-t3.y, t3.x) : make_float2(t3.y, -t3.x);
    v[0] = cadd(t0, t2);
    v[2] = csub(t0, t2);
    v[1] = cadd(t1, t3r);
    v[3] = csub(t1, t3r);
    float2 w1 = tw[t], w2 = tw[2*t];
    v[1] = cmul(v[1], w1);
    v[2] = cmul(v[2], w2);
    v[3] = cmul(v[3], cmul(w1, w2));
}

// Paired forward FFT: two independent 128-pt FFTs interleaved for ILP.
template<int DIR>
__device__ __forceinline__ void warp_fft128_x2(float2 va[4], float2 vb[4],
                                               const float2* __restrict__ tw, int t) {
    fft_prelude<DIR>(va, tw, t);
    fft_prelude<DIR>(vb, tw, t);
#pragma unroll
    for (int d = 16; d >= 1; d >>= 1) {
        int m = (t & (d-1)) * (16/d);
        float2 w = tw[4*m];
        bool hi = (t & d) != 0;
        float s = hi ? -1.f : 1.f;
#pragma unroll
        for (int r = 0; r < 4; r++) {
            float2 pa, pb;
            pa.x = __shfl_xor_sync(0xffffffffu, va[r].x, d);
            pa.y = __shfl_xor_sync(0xffffffffu, va[r].y, d);
            pb.x = __shfl_xor_sync(0xffffffffu, vb[r].x, d);
            pb.y = __shfl_xor_sync(0xffffffffu, vb[r].y, d);
            float2 ta = make_float2(pa.x + s*va[r].x, pa.y + s*va[r].y);
            float2 tb = make_float2(pb.x + s*vb[r].x, pb.y + s*vb[r].y);
            va[r] = hi ? cmul(ta, w) : ta;
            vb[r] = hi ? cmul(tb, w) : tb;
        }
    }
}

// Mirror-DIT inverse: consumes digit-reversed layout, produces natural order.
__device__ __forceinline__ void warp_ifft128_rev(float2 v[4], const float2* __restrict__ twp, int t) {
#pragma unroll
    for (int d = 1; d <= 16; d <<= 1) {
        int m = (t & (d-1)) * (16/d);
        float2 w = twp[4*m];
        bool hi = (t & d) != 0;
#pragma unroll
        for (int r = 0; r < 4; r++) {
            float2 u = hi ? cmul(v[r], w) : v[r];
            float2 p;
            p.x = __shfl_xor_sync(0xffffffffu, u.x, d);
            p.y = __shfl_xor_sync(0xffffffffu, u.y, d);
            v[r] = hi ? csub(p, u) : cadd(u, p);
        }
    }
    float2 w1 = twp[t], w2 = twp[2*t];
    v[1] = cmul(v[1], w1);
    v[2] = cmul(v[2], w2);
    v[3] = cmul(v[3], cmul(w1, w2));
    float2 t0 = cadd(v[0], v[2]), t1 = csub(v[0], v[2]);
    float2 t2 = cadd(v[1], v[3]), t3 = csub(v[1], v[3]);
    float2 t3r = make_float2(-t3.y, t3.x);
    v[0] = cadd(t0, t2);
    v[1] = cadd(t1, t3r);
    v[2] = csub(t0, t2);
    v[3] = csub(t1, t3r);
}

// ---------------------------------------------------------------- zero scratch
__global__ void k_zero() {
    int i = blockIdx.x * blockDim.x + threadIdx.x;
    float4* p = (float4*)d_ras;
    int n4 = 6*VOL/4;
    for (int k = i; k < n4; k += gridDim.x * blockDim.x)
        p[k] = make_float4(0.f, 0.f, 0.f, 0.f);
    if (i < 2) d_accum[i] = 0.f;
}

// ---------------------------------------------------------------- scatter
__global__ void k_scatter(const float* __restrict__ V, const float* __restrict__ N) {
    int id = blockIdx.x * blockDim.x + threadIdx.x;
    if (id >= 2*NPTS) return;
    int b = id >> 16;
    float px = V[3*id+0]*128.f, py = V[3*id+1]*128.f, pz = V[3*id+2]*128.f;
    int ix0 = max(0, min(127, (int)floorf(px)));
    int iy0 = max(0, min(127, (int)floorf(py)));
    int iz0 = max(0, min(127, (int)floorf(pz)));
    float fx = px - (float)ix0, fy = py - (float)iy0, fz = pz - (float)iz0;
    int ix[2] = {ix0, (ix0+1)&127};
    int iy[2] = {iy0, (iy0+1)&127};
    int iz[2] = {iz0, (iz0+1)&127};
    float wx[2] = {1.f-fx, fx}, wy[2] = {1.f-fy, fy}, wz[2] = {1.f-fz, fz};
    float nx = N[3*id+0], ny = N[3*id+1], nz = N[3*id+2];
    float* r = d_ras + (size_t)b*3*VOL;
#pragma unroll
    for (int cx = 0; cx < 2; cx++)
#pragma unroll
        for (int cy = 0; cy < 2; cy++)
#pragma unroll
            for (int cz = 0; cz < 2; cz++) {
                int sp = (ix[cx]*NRES + iy[cy])*NRES + iz[cz];
                float w = wx[cx]*wy[cy]*wz[cz];
                atomicAdd(r + sp,          w*nx);
                atomicAdd(r + VOL + sp,    w*ny);
                atomicAdd(r + 2*VOL + sp,  w*nz);
            }
}

// --------------- K1: packed-pair real z-FFTs + Hermitian split + y-FFT
// One block per (bc,x) plane. Dyn smem: float2 P[64 pairs][K1PD] (full 128
// permuted-kz spectrum per pair; stores and loads conflict-free).
__global__ void __launch_bounds__(512) k_fwdZY() {
    extern __shared__ float2 sh[];              // 64 * K1PD float2
    __shared__ float2 tw[64];
    int tid = threadIdx.x, w = tid >> 5, t = tid & 31;
    build_tw64(tw, tid, -1.f);
    __syncthreads();
    int x = blockIdx.x, bc = blockIdx.y;
    const float* base = d_ras + (size_t)(bc*NRES + x) * NRES * NRES;
    // stage 1: 64 packed pairs (y=2m, 2m+1) -> one complex FFT each
    for (int j = 0; j < 4; j++) {
        int m = w + 16*j;
        const float* inA = base + (2*m)*NRES;
        const float* inB = inA + NRES;
        float2 v[4];
#pragma unroll
        for (int r = 0; r < 4; r++) v[r] = make_float2(inA[t + 32*r], inB[t + 32*r]);
        warp_fft128<0>(v, tw, t);
#pragma unroll
        for (int r = 0; r < 4; r++) sh[m*K1PD + t + 32*r] = v[r];   // permuted kz, cf
    }
    __syncthreads();
    // stage 2: 65 y-lines; split pair spectra on load (Hermitian symmetry)
    float2* dstp = d_sp + (size_t)(bc*NRES + x) * NKZ * NRES;
    int half = t >> 1;
    bool odd = (t & 1) != 0;
    for (int kz = w; kz < NKZ; kz += 16) {
        int a1 = paddr(kz);
        int a2 = paddr((128 - kz) & 127);
        float2 v[4];
#pragma unroll
        for (int r = 0; r < 4; r++) {
            int m = half + 16*r;                 // y = t+32r, m = y>>1, parity = t&1
            float2 P1 = sh[m*K1PD + a1];
            float2 P2 = sh[m*K1PD + a2];
            if (!odd) v[r] = make_float2(0.5f*(P1.x + P2.x), 0.5f*(P1.y - P2.y));
            else      v[r] = make_float2(0.5f*(P1.y + P2.y), 0.5f*(P2.x - P1.x));
        }
        warp_fft128<0>(v, tw, t);
        float2* dst = dstp + kz*NRES;
#pragma unroll
        for (int r = 0; r < 4; r++) dst[t + 32*r] = v[r];   // permuted ky, coalesced
    }
}

// ------------- K2: paired fwd x-FFTs + spectral combine + mirror-DIT inverse
__global__ void __launch_bounds__(512, 2) k_specX() {
    extern __shared__ float2 tile[];            // 2 * K2TS float2 (~35 KB)
    __shared__ float2 twf[64];
    __shared__ float2 twi[64];
    int tid = threadIdx.x, l = tid >> 5, t = tid & 31;
    build_tw64(twf, tid, -1.f);
    if (tid >= 64 && tid < 128) build_tw64(twi, tid - 64, 1.f);
    int c = blockIdx.x, kz = blockIdx.y, b = blockIdx.z;
    int kya0 = K2L*c;
    const float TWOPI = 6.28318530717958647f;
    float fz = (float)kz;
    float2* tileX  = tile;
    float2* tileYZ = tile + K2TS;
    {
        const float2* src0 = d_sp + ((size_t)(b*3 + 0)*NRES*NKZ + kz)*NRES + kya0;
        const float2* src1 = src0 + (size_t)NRES*NKZ*NRES;
        const float2* src2 = src1 + (size_t)NRES*NKZ*NRES;
        for (int i = tid; i < 128*K2L; i += 512) {
            int xx = i >> 4, kyl = i & 15;
            int kya = kya0 + kyl;
            int fyi = 4*bitrev5(kya & 31) + (kya >> 5);
            float fy = (fyi < 64) ? (float)fyi : (float)(fyi - 128);
            size_t off = (size_t)xx*NKZ*NRES + kyl;
            float2 e1 = src1[off];
            float2 e2 = src2[off];
            tileX[xx*17 + kyl] = src0[off];
            tileYZ[xx*17 + kyl] = make_float2(TWOPI*(fy*e1.x + fz*e2.x),
                                              TWOPI*(fy*e1.y + fz*e2.y));
        }
    }
    __syncthreads();
    int kya = kya0 + l;
    int fyi = 4*bitrev5(kya & 31) + (kya >> 5);
    float fy = (fyi < 64) ? (float)fyi : (float)(fyi - 128);
    int u = bitrev5(t);
    float2 vX[4], vYZ[4];
#pragma unroll
    for (int r = 0; r < 4; r++) {
        vX[r]  = tileX[(t + 32*r)*17 + l];
        vYZ[r] = tileYZ[(t + 32*r)*17 + l];
    }
    warp_fft128_x2<0>(vX, vYZ, twf, t);
    float2 P[4];
#pragma unroll
    for (int r = 0; r < 4; r++) {
        int kx = 4*u + r;
        float fx = (float)(kx < 64 ? kx : kx - 128);
        float wx = TWOPI * fx;
        float2 acc = make_float2(wx*vX[r].x + vYZ[r].x, wx*vX[r].y + vYZ[r].y);
        float d2 = fx*fx + fy*fy + fz*fz;
        float G = expf(-0.01220703125f * d2);            // 0.5*(sig*2/128)^2
        float L = -39.478417604357434f * d2 + 1e-6f;     // -4*pi^2*|f|^2 + eps
        P[r] = make_float2(G*acc.y/L, -G*acc.x/L);       // -i*G*acc/L
        if (kx == 0 && fyi == 0 && kz == 0) P[r] = make_float2(0.f, 0.f);
    }
    warp_ifft128_rev(P, twi, t);                // -> natural x order
    __syncthreads();
#pragma unroll
    for (int r = 0; r < 4; r++) tileX[(t + 32*r)*17 + l] = P[r];
    __syncthreads();
    float2* dst = d_inv1 + (size_t)(b*NKZ + kz)*NRES*NRES + kya0;
    for (int i = tid; i < 128*K2L; i += 512) {
        int xx = i >> 4, kyl = i & 15;
        dst[(size_t)xx*NRES + kyl] = tileX[xx*17 + kyl];
    }
}

// --------------- K3: inverse y-FFT (mirror-DIT) + packed-pair C2R z-FFTs
__global__ void __launch_bounds__(512) k_invYZ() {
    extern __shared__ float2 sh[];              // 128*65 float2 : sh[y][kz]
    __shared__ float2 twi[64];
    int tid = threadIdx.x, w = tid >> 5, t = tid & 31;
    build_tw64(twi, tid, 1.f);
    __syncthreads();
    int x = blockIdx.x, b = blockIdx.y;
    // stage 1: 65 ky-lines (permuted-ky input -> natural y out)
    for (int kz = w; kz < NKZ; kz += 16) {
        const float2* in = d_inv1 + ((size_t)(b*NKZ + kz)*NRES + x)*NRES;
        float2 v[4];
#pragma unroll
        for (int r = 0; r < 4; r++) v[r] = in[t + 32*r];
        warp_ifft128_rev(v, twi, t);            // natural y = t+32r
#pragma unroll
        for (int r = 0; r < 4; r++) sh[(t + 32*r)*NKZ + kz] = v[r];
    }
    __syncthreads();
    // stage 2: 64 packed C2R pairs: G = S_{2m} + i*S_{2m+1}, one inverse FFT
    const float sc = 1.0f / 2097152.0f;         // 1/128^3
    float* outb = d_phi + (size_t)(b*NRES + x) * NRES * NRES;
    for (int j = 0; j < 4; j++) {
        int m = w + 16*j;
        const float2* rowA = sh + (2*m)*NKZ;
        const float2* rowB = rowA + NKZ;
        float2 v[4];
#pragma unroll
        for (int r = 0; r < 4; r++) {
            int k = t + 32*r;
            if (k <= 64) {
                float2 A = rowA[k], B = rowB[k];
                v[r] = make_float2(A.x - B.y, A.y + B.x);
            } else {
                int k2 = 128 - k;
                float2 A = rowA[k2], B = rowB[k2];
                v[r] = make_float2(A.x + B.y, B.x - A.y);
            }
        }
        warp_fft128<1>(v, twi, t);
        float* oA = outb + (2*m)*NRES;
        float* oB = oA + NRES;
#pragma unroll
        for (int r = 0; r < 4; r++) {
            oA[t + 32*r] = v[r].x * sc;         // y=2m,   permuted z
            oB[t + 32*r] = v[r].y * sc;         // y=2m+1, permuted z
        }
    }
}

// ---------------------------------------------------------------- gather + mean
__global__ void k_gather(const float* __restrict__ V) {
    __shared__ float red[256];
    int id = blockIdx.x * 256 + threadIdx.x;    // 131072; b uniform per block
    int b = id >> 16;
    float px = V[3*id+0]*128.f, py = V[3*id+1]*128.f, pz = V[3*id+2]*128.f;
    int ix0 = max(0, min(127, (int)floorf(px)));
    int iy0 = max(0, min(127, (int)floorf(py)));
    int iz0 = max(0, min(127, (int)floorf(pz)));
    float fx = px - (float)ix0, fy = py - (float)iy0, fz = pz - (float)iz0;
    int ix[2] = {ix0, (ix0+1)&127};
    int iy[2] = {iy0, (iy0+1)&127};
    int az[2] = {paddr(iz0), paddr((iz0+1)&127)};
    float wx[2] = {1.f-fx, fx}, wy[2] = {1.f-fy, fy}, wz[2] = {1.f-fz, fz};
    const float* ph = d_phi + (size_t)b*VOL;
    float fv = 0.f;
#pragma unroll
    for (int cx = 0; cx < 2; cx++)
#pragma unroll
        for (int cy = 0; cy < 2; cy++)
#pragma unroll
            for (int cz = 0; cz < 2; cz++)
                fv += wx[cx]*wy[cy]*wz[cz] * ph[(ix[cx]*NRES + iy[cy])*NRES + az[cz]];
    red[threadIdx.x] = fv;
    __syncthreads();
    for (int s = 128; s > 0; s >>= 1) {
        if (threadIdx.x < s) red[threadIdx.x] += red[threadIdx.x + s];
        __syncthreads();
    }
    if (threadIdx.x == 0) atomicAdd(&d_accum[b], red[0]);
}

// ---------------------------------------------------------------- finalize
__global__ void k_final(float* __restrict__ out) {
    int id = blockIdx.x * 256 + threadIdx.x;    // 4194304 total
    int b = id >> 21;
    int z = id & 127;
    int base = id - z;
    float off  = d_accum[b] * (1.0f/65536.0f);
    float p000 = d_phi[(size_t)b * VOL];        // paddr(0)=0
    float s = 0.5f / fabsf(p000 - off);
    out[id] = -(d_phi[base + paddr(z)] - off) * s;
}

// ---------------------------------------------------------------- launch
extern "C" void kernel_launch(void* const* d_in, const int* in_sizes, int n_in,
                              void* d_out, int out_size) {
    const float* V = (const float*)d_in[0];
    const float* N = (const float*)d_in[1];
    float* out = (float*)d_out;

    const int k1Bytes = 64*K1PD*sizeof(float2);       // 66048
    const int k3Bytes = NRES*NKZ*sizeof(float2);      // 66560
    const int k2Bytes = 2*K2TS*sizeof(float2);        // 34816
    cudaFuncSetAttribute(k_fwdZY, cudaFuncAttributeMaxDynamicSharedMemorySize, k1Bytes);
    cudaFuncSetAttribute(k_invYZ, cudaFuncAttributeMaxDynamicSharedMemorySize, k3Bytes);
    cudaFuncSetAttribute(k_specX, cudaFuncAttributeMaxDynamicSharedMemorySize, k2Bytes);

    k_zero<<<4096, 256>>>();
    k_scatter<<<512, 256>>>(V, N);
    k_fwdZY<<<dim3(128, 6), 512, k1Bytes>>>();        // 768 planes
    k_specX<<<dim3(8, 65, 2), 512, k2Bytes>>>();      // 1040 tiles of 16 lines
    k_invYZ<<<dim3(128, 2), 512, k3Bytes>>>();        // 256 planes
    k_gather<<<512, 256>>>(V);
    k_final<<<16384, 256>>>(out);
}

// round 7
// speedup vs baseline: 1.3748x; 1.0276x over previous
#include <cuda_runtime.h>
#include <math.h>

// DPSR: scatter -> 3D rFFT -> spectral Poisson solve -> 3D irFFT -> gather/normalize
// Fused pipeline (3 FFT kernels):
//   K1 k_fwdZY : per (bc,x) plane: packed-pair real z-FFTs (64 complex FFTs for
//                128 real lines) + Hermitian split on load + y-FFT. ras -> d_sp
//   K2 k_specX : channels 1,2 pre-combined with (2pi*fy, 2pi*fz) at load ->
//                sequential X / YZ fwd FFTs (X spectrum parked in private smem
//                column) + combine + mirror-DIT inverse. 256thr/8 lines, 5 blk/SM.
//   K3 k_invYZ : per (b,x) plane: inverse y-FFT (mirror-DIT) + packed-pair C2R
//                z-FFTs (64 complex FFTs emit 128 real lines). -> d_phi
//
// Axis conventions:
//   - ky axis of d_sp/d_inv1 DIGIT-REVERSED: address a holds freq
//     f = 4*bitrev5(a&31) + (a>>5). Writers store lane t reg r at a=t+32r.
//   - z axis of d_phi digit-reversed the same way; gather/final permute addresses.
//   - kz truncated natural (0..64); x, y natural.

#define NRES 128
#define NKZ  65
#define VOL  (NRES*NRES*NRES)
#define NPTS 65536
#define K2L  8           // kya lines per K2 block
#define K2P  9           // K2 tile pad stride
#define K2TS (128*K2P)   // padded tile size (float2) per channel
#define K1PD 129         // K1 stage-1 smem row stride (float2), odd

__device__ float  d_ras[6*VOL];                 // [bc][x][y][z]
__device__ float2 d_sp[6*NRES*NKZ*NRES];        // [bc][x][kz][kya]
__device__ float2 d_inv1[2*NKZ*NRES*NRES];      // [b][kz][x][kya]
__device__ float  d_phi[2*VOL];                 // [b][x][y][za]
__device__ float  d_accum[2];

__device__ __forceinline__ float2 cmul(float2 a, float2 b) {
    return make_float2(a.x*b.x - a.y*b.y, a.x*b.y + a.y*b.x);
}
__device__ __forceinline__ float2 cadd(float2 a, float2 b) { return make_float2(a.x+b.x, a.y+b.y); }
__device__ __forceinline__ float2 csub(float2 a, float2 b) { return make_float2(a.x-b.x, a.y-b.y); }
__device__ __forceinline__ int bitrev5(int t) { return (int)(__brev((unsigned)t) >> 27); }
__device__ __forceinline__ int paddr(int k) { return bitrev5(k >> 2) + ((k & 3) << 5); }

__device__ __forceinline__ void build_tw64(float2* tw, int tid, float sign) {
    if (tid < 64) {
        float s, c;
        sincosf(sign * 6.28318530717958647f * (float)tid * (1.0f/128.0f), &s, &c);
        tw[tid] = make_float2(c, s);
    }
}

// Natural-input warp FFT. Lane t holds v[r]=x[t+32r]; out v[r]=X[4*bitrev5(t)+r].
template<int DIR>
__device__ __forceinline__ void warp_fft128(float2 v[4], const float2* __restrict__ tw, int t) {
    float2 t0 = cadd(v[0], v[2]);
    float2 t1 = csub(v[0], v[2]);
    float2 t2 = cadd(v[1], v[3]);
    float2 t3 = csub(v[1], v[3]);
    float2 t3r = DIR ? make_float2(-t3.y, t3.x) : make_float2(t3.y, -t3.x);
    v[0] = cadd(t0, t2);
    v[2] = csub(t0, t2);
    v[1] = cadd(t1, t3r);
    v[3] = csub(t1, t3r);
    float2 w1 = tw[t], w2 = tw[2*t];
    v[1] = cmul(v[1], w1);
    v[2] = cmul(v[2], w2);
    v[3] = cmul(v[3], cmul(w1, w2));
#pragma unroll
    for (int d = 16; d >= 1; d >>= 1) {
        int m = (t & (d-1)) * (16/d);
        float2 w = tw[4*m];
        bool hi = (t & d) != 0;
        float s = hi ? -1.f : 1.f;
#pragma unroll
        for (int r = 0; r < 4; r++) {
            float2 p;
            p.x = __shfl_xor_sync(0xffffffffu, v[r].x, d);
            p.y = __shfl_xor_sync(0xffffffffu, v[r].y, d);
            float2 tmp = make_float2(p.x + s*v[r].x, p.y + s*v[r].y);
            v[r] = hi ? cmul(tmp, w) : tmp;
        }
    }
}

// Mirror-DIT inverse: consumes digit-reversed layout, produces natural order.
__device__ __forceinline__ void warp_ifft128_rev(float2 v[4], const float2* __restrict__ twp, int t) {
#pragma unroll
    for (int d = 1; d <= 16; d <<= 1) {
        int m = (t & (d-1)) * (16/d);
        float2 w = twp[4*m];
        bool hi = (t & d) != 0;
#pragma unroll
        for (int r = 0; r < 4; r++) {
            float2 u = hi ? cmul(v[r], w) : v[r];
            float2 p;
            p.x = __shfl_xor_sync(0xffffffffu, u.x, d);
            p.y = __shfl_xor_sync(0xffffffffu, u.y, d);
            v[r] = hi ? csub(p, u) : cadd(u, p);
        }
    }
    float2 w1 = twp[t], w2 = twp[2*t];
    v[1] = cmul(v[1], w1);
    v[2] = cmul(v[2], w2);
    v[3] = cmul(v[3], cmul(w1, w2));
    float2 t0 = cadd(v[0], v[2]), t1 = csub(v[0], v[2]);
    float2 t2 = cadd(v[1], v[3]), t3 = csub(v[1], v[3]);
    float2 t3r = make_float2(-t3.y, t3.x);
    v[0] = cadd(t0, t2);
    v[1] = cadd(t1, t3r);
    v[2] = csub(t0, t2);
    v[3] = csub(t1, t3r);
}

// ---------------------------------------------------------------- zero scratch
__global__ void k_zero() {
    int i = blockIdx.x * blockDim.x + threadIdx.x;
    float4* p = (float4*)d_ras;
    int n4 = 6*VOL/4;
    for (int k = i; k < n4; k += gridDim.x * blockDim.x)
        p[k] = make_float4(0.f, 0.f, 0.f, 0.f);
    if (i < 2) d_accum[i] = 0.f;
}

// ---------------------------------------------------------------- scatter
__global__ void k_scatter(const float* __restrict__ V, const float* __restrict__ N) {
    int id = blockIdx.x * blockDim.x + threadIdx.x;
    if (id >= 2*NPTS) return;
    int b = id >> 16;
    float px = V[3*id+0]*128.f, py = V[3*id+1]*128.f, pz = V[3*id+2]*128.f;
    int ix0 = max(0, min(127, (int)floorf(px)));
    int iy0 = max(0, min(127, (int)floorf(py)));
    int iz0 = max(0, min(127, (int)floorf(pz)));
    float fx = px - (float)ix0, fy = py - (float)iy0, fz = pz - (float)iz0;
    int ix[2] = {ix0, (ix0+1)&127};
    int iy[2] = {iy0, (iy0+1)&127};
    int iz[2] = {iz0, (iz0+1)&127};
    float wx[2] = {1.f-fx, fx}, wy[2] = {1.f-fy, fy}, wz[2] = {1.f-fz, fz};
    float nx = N[3*id+0], ny = N[3*id+1], nz = N[3*id+2];
    float* r = d_ras + (size_t)b*3*VOL;
#pragma unroll
    for (int cx = 0; cx < 2; cx++)
#pragma unroll
        for (int cy = 0; cy < 2; cy++)
#pragma unroll
            for (int cz = 0; cz < 2; cz++) {
                int sp = (ix[cx]*NRES + iy[cy])*NRES + iz[cz];
                float w = wx[cx]*wy[cy]*wz[cz];
                atomicAdd(r + sp,          w*nx);
                atomicAdd(r + VOL + sp,    w*ny);
                atomicAdd(r + 2*VOL + sp,  w*nz);
            }
}

// --------------- K1: packed-pair real z-FFTs + Hermitian split + y-FFT
__global__ void __launch_bounds__(512, 3) k_fwdZY() {
    extern __shared__ float2 sh[];              // 64 * K1PD float2
    __shared__ float2 tw[64];
    int tid = threadIdx.x, w = tid >> 5, t = tid & 31;
    build_tw64(tw, tid, -1.f);
    __syncthreads();
    int x = blockIdx.x, bc = blockIdx.y;
    const float* base = d_ras + (size_t)(bc*NRES + x) * NRES * NRES;
    // stage 1: 64 packed pairs (y=2m, 2m+1) -> one complex FFT each
    for (int j = 0; j < 4; j++) {
        int m = w + 16*j;
        const float* inA = base + (2*m)*NRES;
        const float* inB = inA + NRES;
        float2 v[4];
#pragma unroll
        for (int r = 0; r < 4; r++) v[r] = make_float2(inA[t + 32*r], inB[t + 32*r]);
        warp_fft128<0>(v, tw, t);
#pragma unroll
        for (int r = 0; r < 4; r++) sh[m*K1PD + t + 32*r] = v[r];   // permuted kz, cf
    }
    __syncthreads();
    // stage 2: 65 y-lines; split pair spectra on load (Hermitian symmetry)
    float2* dstp = d_sp + (size_t)(bc*NRES + x) * NKZ * NRES;
    int half = t >> 1;
    bool odd = (t & 1) != 0;
    for (int kz = w; kz < NKZ; kz += 16) {
        int a1 = paddr(kz);
        int a2 = paddr((128 - kz) & 127);
        float2 v[4];
#pragma unroll
        for (int r = 0; r < 4; r++) {
            int m = half + 16*r;                 // y = t+32r, m = y>>1, parity = t&1
            float2 P1 = sh[m*K1PD + a1];
            float2 P2 = sh[m*K1PD + a2];
            if (!odd) v[r] = make_float2(0.5f*(P1.x + P2.x), 0.5f*(P1.y - P2.y));
            else      v[r] = make_float2(0.5f*(P1.y + P2.y), 0.5f*(P2.x - P1.x));
        }
        warp_fft128<0>(v, tw, t);
        float2* dst = dstp + kz*NRES;
#pragma unroll
        for (int r = 0; r < 4; r++) dst[t + 32*r] = v[r];   // permuted ky, coalesced
    }
}

// ------------- K2: sequential fwd X/YZ FFTs + combine + mirror-DIT inverse
// 256 threads = 8 warps; warp l handles line kya = kya0 + l. X spectrum parked
// in the warp's private smem column between the two forward FFTs (no sync).
__global__ void __launch_bounds__(256, 5) k_specX() {
    extern __shared__ float2 tile[];            // 2 * K2TS float2 (18 KB)
    __shared__ float2 twf[64];
    __shared__ float2 twi[64];
    int tid = threadIdx.x, l = tid >> 5, t = tid & 31;
    build_tw64(twf, tid, -1.f);
    if (tid >= 64 && tid < 128) build_tw64(twi, tid - 64, 1.f);
    int c = blockIdx.x, kz = blockIdx.y, b = blockIdx.z;
    int kya0 = K2L*c;
    const float TWOPI = 6.28318530717958647f;
    float fz = (float)kz;
    float2* tileX  = tile;
    float2* tileYZ = tile + K2TS;
    // ---- load phase: ch0 raw; ch1,ch2 combined with line weights
    {
        const float2* src0 = d_sp + ((size_t)(b*3 + 0)*NRES*NKZ + kz)*NRES + kya0;
        const float2* src1 = src0 + (size_t)NRES*NKZ*NRES;
        const float2* src2 = src1 + (size_t)NRES*NKZ*NRES;
        for (int i = tid; i < 128*K2L; i += 256) {
            int xx = i >> 3, kyl = i & 7;
            int kya = kya0 + kyl;
            int fyi = 4*bitrev5(kya & 31) + (kya >> 5);
            float fy = (fyi < 64) ? (float)fyi : (float)(fyi - 128);
            size_t off = (size_t)xx*NKZ*NRES + kyl;
            float2 e1 = src1[off];
            float2 e2 = src2[off];
            tileX[xx*K2P + kyl] = src0[off];
            tileYZ[xx*K2P + kyl] = make_float2(TWOPI*(fy*e1.x + fz*e2.x),
                                               TWOPI*(fy*e1.y + fz*e2.y));
        }
    }
    __syncthreads();
    int kya = kya0 + l;
    int fyi = 4*bitrev5(kya & 31) + (kya >> 5);
    float fy = (fyi < 64) ? (float)fyi : (float)(fyi - 128);
    int u = bitrev5(t);
    // fwd FFT of X channel; park spectrum in own column (slots we just read)
    {
        float2 vX[4];
#pragma unroll
        for (int r = 0; r < 4; r++) vX[r] = tileX[(t + 32*r)*K2P + l];
        warp_fft128<0>(vX, twf, t);
#pragma unroll
        for (int r = 0; r < 4; r++) tileX[(t + 32*r)*K2P + l] = vX[r];
    }
    // fwd FFT of YZ channel, then combine with parked X spectrum
    float2 v[4];
#pragma unroll
    for (int r = 0; r < 4; r++) v[r] = tileYZ[(t + 32*r)*K2P + l];
    warp_fft128<0>(v, twf, t);
#pragma unroll
    for (int r = 0; r < 4; r++) {
        float2 xs = tileX[(t + 32*r)*K2P + l];
        int kx = 4*u + r;
        float fx = (float)(kx < 64 ? kx : kx - 128);
        float wx = TWOPI * fx;
        float2 acc = make_float2(wx*xs.x + v[r].x, wx*xs.y + v[r].y);
        float d2 = fx*fx + fy*fy + fz*fz;
        float G = expf(-0.01220703125f * d2);            // 0.5*(sig*2/128)^2
        float L = -39.478417604357434f * d2 + 1e-6f;     // -4*pi^2*|f|^2 + eps
        v[r] = make_float2(G*acc.y/L, -G*acc.x/L);       // -i*G*acc/L
        if (kx == 0 && fyi == 0 && kz == 0) v[r] = make_float2(0.f, 0.f);
    }
    warp_ifft128_rev(v, twi, t);                // -> natural x order
#pragma unroll
    for (int r = 0; r < 4; r++) tileX[(t + 32*r)*K2P + l] = v[r];   // own column
    __syncthreads();
    float2* dst = d_inv1 + (size_t)(b*NKZ + kz)*NRES*NRES + kya0;
    for (int i = tid; i < 128*K2L; i += 256) {
        int xx = i >> 3, kyl = i & 7;
        dst[(size_t)xx*NRES + kyl] = tileX[xx*K2P + kyl];
    }
}

// --------------- K3: inverse y-FFT (mirror-DIT) + packed-pair C2R z-FFTs
__global__ void __launch_bounds__(512, 3) k_invYZ() {
    extern __shared__ float2 sh[];              // 128*65 float2 : sh[y][kz]
    __shared__ float2 twi[64];
    int tid = threadIdx.x, w = tid >> 5, t = tid & 31;
    build_tw64(twi, tid, 1.f);
    __syncthreads();
    int x = blockIdx.x, b = blockIdx.y;
    // stage 1: 65 ky-lines (permuted-ky input -> natural y out)
    for (int kz = w; kz < NKZ; kz += 16) {
        const float2* in = d_inv1 + ((size_t)(b*NKZ + kz)*NRES + x)*NRES;
        float2 v[4];
#pragma unroll
        for (int r = 0; r < 4; r++) v[r] = in[t + 32*r];
        warp_ifft128_rev(v, twi, t);            // natural y = t+32r
#pragma unroll
        for (int r = 0; r < 4; r++) sh[(t + 32*r)*NKZ + kz] = v[r];
    }
    __syncthreads();
    // stage 2: 64 packed C2R pairs: G = S_{2m} + i*S_{2m+1}, one inverse FFT
    const float sc = 1.0f / 2097152.0f;         // 1/128^3
    float* outb = d_phi + (size_t)(b*NRES + x) * NRES * NRES;
    for (int j = 0; j < 4; j++) {
        int m = w + 16*j;
        const float2* rowA = sh + (2*m)*NKZ;
        const float2* rowB = rowA + NKZ;
        float2 v[4];
#pragma unroll
        for (int r = 0; r < 4; r++) {
            int k = t + 32*r;
            if (k <= 64) {
                float2 A = rowA[k], B = rowB[k];
                v[r] = make_float2(A.x - B.y, A.y + B.x);
            } else {
                int k2 = 128 - k;
                float2 A = rowA[k2], B = rowB[k2];
                v[r] = make_float2(A.x + B.y, B.x - A.y);
            }
        }
        warp_fft128<1>(v, twi, t);
        float* oA = outb + (2*m)*NRES;
        float* oB = oA + NRES;
#pragma unroll
        for (int r = 0; r < 4; r++) {
            oA[t + 32*r] = v[r].x * sc;         // y=2m,   permuted z
            oB[t + 32*r] = v[r].y * sc;         // y=2m+1, permuted z
        }
    }
}

// ---------------------------------------------------------------- gather + mean
__global__ void k_gather(const float* __restrict__ V) {
    __shared__ float red[256];
    int id = blockIdx.x * 256 + threadIdx.x;    // 131072; b uniform per block
    int b = id >> 16;
    float px = V[3*id+0]*128.f, py = V[3*id+1]*128.f, pz = V[3*id+2]*128.f;
    int ix0 = max(0, min(127, (int)floorf(px)));
    int iy0 = max(0, min(127, (int)floorf(py)));
    int iz0 = max(0, min(127, (int)floorf(pz)));
    float fx = px - (float)ix0, fy = py - (float)iy0, fz = pz - (float)iz0;
    int ix[2] = {ix0, (ix0+1)&127};
    int iy[2] = {iy0, (iy0+1)&127};
    int az[2] = {paddr(iz0), paddr((iz0+1)&127)};
    float wx[2] = {1.f-fx, fx}, wy[2] = {1.f-fy, fy}, wz[2] = {1.f-fz, fz};
    const float* ph = d_phi + (size_t)b*VOL;
    float fv = 0.f;
#pragma unroll
    for (int cx = 0; cx < 2; cx++)
#pragma unroll
        for (int cy = 0; cy < 2; cy++)
#pragma unroll
            for (int cz = 0; cz < 2; cz++)
                fv += wx[cx]*wy[cy]*wz[cz] * ph[(ix[cx]*NRES + iy[cy])*NRES + az[cz]];
    red[threadIdx.x] = fv;
    __syncthreads();
    for (int s = 128; s > 0; s >>= 1) {
        if (threadIdx.x < s) red[threadIdx.x] += red[threadIdx.x + s];
        __syncthreads();
    }
    if (threadIdx.x == 0) atomicAdd(&d_accum[b], red[0]);
}

// ---------------------------------------------------------------- finalize
__global__ void k_final(float* __restrict__ out) {
    int id = blockIdx.x * 256 + threadIdx.x;    // 4194304 total
    int b = id >> 21;
    int z = id & 127;
    int base = id - z;
    float off  = d_accum[b] * (1.0f/65536.0f);
    float p000 = d_phi[(size_t)b * VOL];        // paddr(0)=0
    float s = 0.5f / fabsf(p000 - off);
    out[id] = -(d_phi[base + paddr(z)] - off) * s;
}

// ---------------------------------------------------------------- launch
extern "C" void kernel_launch(void* const* d_in, const int* in_sizes, int n_in,
                              void* d_out, int out_size) {
    const float* V = (const float*)d_in[0];
    const float* N = (const float*)d_in[1];
    float* out = (float*)d_out;

    const int k1Bytes = 64*K1PD*sizeof(float2);       // 66048
    const int k3Bytes = NRES*NKZ*sizeof(float2);      // 66560
    const int k2Bytes = 2*K2TS*sizeof(float2);        // 18432
    cudaFuncSetAttribute(k_fwdZY, cudaFuncAttributeMaxDynamicSharedMemorySize, k1Bytes);
    cudaFuncSetAttribute(k_invYZ, cudaFuncAttributeMaxDynamicSharedMemorySize, k3Bytes);

    k_zero<<<4096, 256>>>();
    k_scatter<<<512, 256>>>(V, N);
    k_fwdZY<<<dim3(128, 6), 512, k1Bytes>>>();        // 768 planes
    k_specX<<<dim3(16, 65, 2), 256, k2Bytes>>>();     // 2080 tiles of 8 lines
    k_invYZ<<<dim3(128, 2), 512, k3Bytes>>>();        // 256 planes
    k_gather<<<512, 256>>>(V);
    k_final<<<16384, 256>>>(out);
}

// round 8
// speedup vs baseline: 1.7366x; 1.2632x over previous
#include <cuda_runtime.h>
#include <math.h>

// DPSR: scatter -> 3D rFFT -> spectral Poisson solve -> 3D irFFT -> gather/normalize
// Fused pipeline (3 FFT kernels) + spectral cutoff:
//   G = exp(-0.0122*d2) is < 2.5e-11 for fy^2+fz^2 > 2000 at any kx -> those
//   (ky,kz) lines produce ~0; skip their FFTs/loads and write zeros instead.
//   K1 k_fwdZY : packed-pair real z-FFTs + Hermitian split + y-FFT (skip kz>=45)
//   K2 k_specX : per-line cutoff; sequential X/YZ fwd FFTs + combine + mirror-
//                DIT inverse; skipped lines write zero columns.
//   K3 k_invYZ : inverse y-FFT (zero-fill kz>=45) + packed-pair C2R z-FFTs.
//
// Axis conventions:
//   - ky axis of d_sp/d_inv1 DIGIT-REVERSED: address a holds freq
//     f = 4*bitrev5(a&31) + (a>>5). Writers store lane t reg r at a=t+32r.
//   - z axis of d_phi digit-reversed the same way; gather/final permute addresses.
//   - kz truncated natural (0..64); x, y natural.

#define NRES 128
#define NKZ  65
#define VOL  (NRES*NRES*NRES)
#define NPTS 65536
#define K2L  8           // kya lines per K2 block
#define K2P  9           // K2 tile pad stride
#define K2TS (128*K2P)   // padded tile size (float2) per channel
#define K1PD 129         // K1 stage-1 smem row stride (float2), odd
#define CUT2 2000.0f     // skip line if fy^2+fz^2 > CUT2  (G < 2.5e-11)
#define KZCUT 45         // kz >= KZCUT -> fz^2 > CUT2 for all ky

__device__ float  d_ras[6*VOL];                 // [bc][x][y][z]
__device__ float2 d_sp[6*NRES*NKZ*NRES];        // [bc][x][kz][kya]
__device__ float2 d_inv1[2*NKZ*NRES*NRES];      // [b][kz][x][kya]
__device__ float  d_phi[2*VOL];                 // [b][x][y][za]
__device__ float  d_accum[2];

__device__ __forceinline__ float2 cmul(float2 a, float2 b) {
    return make_float2(a.x*b.x - a.y*b.y, a.x*b.y + a.y*b.x);
}
__device__ __forceinline__ float2 cadd(float2 a, float2 b) { return make_float2(a.x+b.x, a.y+b.y); }
__device__ __forceinline__ float2 csub(float2 a, float2 b) { return make_float2(a.x-b.x, a.y-b.y); }
__device__ __forceinline__ int bitrev5(int t) { return (int)(__brev((unsigned)t) >> 27); }
__device__ __forceinline__ int paddr(int k) { return bitrev5(k >> 2) + ((k & 3) << 5); }

__device__ __forceinline__ void build_tw64(float2* tw, int tid, float sign) {
    if (tid < 64) {
        float s, c;
        sincosf(sign * 6.28318530717958647f * (float)tid * (1.0f/128.0f), &s, &c);
        tw[tid] = make_float2(c, s);
    }
}

// Natural-input warp FFT. Lane t holds v[r]=x[t+32r]; out v[r]=X[4*bitrev5(t)+r].
template<int DIR>
__device__ __forceinline__ void warp_fft128(float2 v[4], const float2* __restrict__ tw, int t) {
    float2 t0 = cadd(v[0], v[2]);
    float2 t1 = csub(v[0], v[2]);
    float2 t2 = cadd(v[1], v[3]);
    float2 t3 = csub(v[1], v[3]);
    float2 t3r = DIR ? make_float2(-t3.y, t3.x) : make_float2(t3.y, -t3.x);
    v[0] = cadd(t0, t2);
    v[2] = csub(t0, t2);
    v[1] = cadd(t1, t3r);
    v[3] = csub(t1, t3r);
    float2 w1 = tw[t], w2 = tw[2*t];
    v[1] = cmul(v[1], w1);
    v[2] = cmul(v[2], w2);
    v[3] = cmul(v[3], cmul(w1, w2));
#pragma unroll
    for (int d = 16; d >= 1; d >>= 1) {
        int m = (t & (d-1)) * (16/d);
        float2 w = tw[4*m];
        bool hi = (t & d) != 0;
        float s = hi ? -1.f : 1.f;
#pragma unroll
        for (int r = 0; r < 4; r++) {
            float2 p;
            p.x = __shfl_xor_sync(0xffffffffu, v[r].x, d);
            p.y = __shfl_xor_sync(0xffffffffu, v[r].y, d);
            float2 tmp = make_float2(p.x + s*v[r].x, p.y + s*v[r].y);
            v[r] = hi ? cmul(tmp, w) : tmp;
        }
    }
}

// Mirror-DIT inverse: consumes digit-reversed layout, produces natural order.
__device__ __forceinline__ void warp_ifft128_rev(float2 v[4], const float2* __restrict__ twp, int t) {
#pragma unroll
    for (int d = 1; d <= 16; d <<= 1) {
        int m = (t & (d-1)) * (16/d);
        float2 w = twp[4*m];
        bool hi = (t & d) != 0;
#pragma unroll
        for (int r = 0; r < 4; r++) {
            float2 u = hi ? cmul(v[r], w) : v[r];
            float2 p;
            p.x = __shfl_xor_sync(0xffffffffu, u.x, d);
            p.y = __shfl_xor_sync(0xffffffffu, u.y, d);
            v[r] = hi ? csub(p, u) : cadd(u, p);
        }
    }
    float2 w1 = twp[t], w2 = twp[2*t];
    v[1] = cmul(v[1], w1);
    v[2] = cmul(v[2], w2);
    v[3] = cmul(v[3], cmul(w1, w2));
    float2 t0 = cadd(v[0], v[2]), t1 = csub(v[0], v[2]);
    float2 t2 = cadd(v[1], v[3]), t3 = csub(v[1], v[3]);
    float2 t3r = make_float2(-t3.y, t3.x);
    v[0] = cadd(t0, t2);
    v[1] = cadd(t1, t3r);
    v[2] = csub(t0, t2);
    v[3] = csub(t1, t3r);
}

// ---------------------------------------------------------------- zero scratch
__global__ void k_zero() {
    int i = blockIdx.x * blockDim.x + threadIdx.x;
    float4* p = (float4*)d_ras;
    int n4 = 6*VOL/4;
    for (int k = i; k < n4; k += gridDim.x * blockDim.x)
        p[k] = make_float4(0.f, 0.f, 0.f, 0.f);
    if (i < 2) d_accum[i] = 0.f;
}

// ---------------------------------------------------------------- scatter
__global__ void k_scatter(const float* __restrict__ V, const float* __restrict__ N) {
    int id = blockIdx.x * blockDim.x + threadIdx.x;
    if (id >= 2*NPTS) return;
    int b = id >> 16;
    float px = V[3*id+0]*128.f, py = V[3*id+1]*128.f, pz = V[3*id+2]*128.f;
    int ix0 = max(0, min(127, (int)floorf(px)));
    int iy0 = max(0, min(127, (int)floorf(py)));
    int iz0 = max(0, min(127, (int)floorf(pz)));
    float fx = px - (float)ix0, fy = py - (float)iy0, fz = pz - (float)iz0;
    int ix[2] = {ix0, (ix0+1)&127};
    int iy[2] = {iy0, (iy0+1)&127};
    int iz[2] = {iz0, (iz0+1)&127};
    float wx[2] = {1.f-fx, fx}, wy[2] = {1.f-fy, fy}, wz[2] = {1.f-fz, fz};
    float nx = N[3*id+0], ny = N[3*id+1], nz = N[3*id+2];
    float* r = d_ras + (size_t)b*3*VOL;
#pragma unroll
    for (int cx = 0; cx < 2; cx++)
#pragma unroll
        for (int cy = 0; cy < 2; cy++)
#pragma unroll
            for (int cz = 0; cz < 2; cz++) {
                int sp = (ix[cx]*NRES + iy[cy])*NRES + iz[cz];
                float w = wx[cx]*wy[cy]*wz[cz];
                atomicAdd(r + sp,          w*nx);
                atomicAdd(r + VOL + sp,    w*ny);
                atomicAdd(r + 2*VOL + sp,  w*nz);
            }
}

// --------------- K1: packed-pair real z-FFTs + Hermitian split + y-FFT
__global__ void __launch_bounds__(512, 3) k_fwdZY() {
    extern __shared__ float2 sh[];              // 64 * K1PD float2
    __shared__ float2 tw[64];
    int tid = threadIdx.x, w = tid >> 5, t = tid & 31;
    build_tw64(tw, tid, -1.f);
    __syncthreads();
    int x = blockIdx.x, bc = blockIdx.y;
    const float* base = d_ras + (size_t)(bc*NRES + x) * NRES * NRES;
    // stage 1: 64 packed pairs (y=2m, 2m+1) -> one complex FFT each
    for (int j = 0; j < 4; j++) {
        int m = w + 16*j;
        const float* inA = base + (2*m)*NRES;
        const float* inB = inA + NRES;
        float2 v[4];
#pragma unroll
        for (int r = 0; r < 4; r++) v[r] = make_float2(inA[t + 32*r], inB[t + 32*r]);
        warp_fft128<0>(v, tw, t);
#pragma unroll
        for (int r = 0; r < 4; r++) sh[m*K1PD + t + 32*r] = v[r];   // permuted kz, cf
    }
    __syncthreads();
    // stage 2: y-lines for kz < KZCUT only (kz >= KZCUT lines are cut by G)
    float2* dstp = d_sp + (size_t)(bc*NRES + x) * NKZ * NRES;
    int half = t >> 1;
    bool odd = (t & 1) != 0;
    for (int kz = w; kz < KZCUT; kz += 16) {
        int a1 = paddr(kz);
        int a2 = paddr((128 - kz) & 127);
        float2 v[4];
#pragma unroll
        for (int r = 0; r < 4; r++) {
            int m = half + 16*r;                 // y = t+32r, m = y>>1, parity = t&1
            float2 P1 = sh[m*K1PD + a1];
            float2 P2 = sh[m*K1PD + a2];
            if (!odd) v[r] = make_float2(0.5f*(P1.x + P2.x), 0.5f*(P1.y - P2.y));
            else      v[r] = make_float2(0.5f*(P1.y + P2.y), 0.5f*(P2.x - P1.x));
        }
        warp_fft128<0>(v, tw, t);
        float2* dst = dstp + kz*NRES;
#pragma unroll
        for (int r = 0; r < 4; r++) dst[t + 32*r] = v[r];   // permuted ky, coalesced
    }
}

// ------------- K2: per-line cutoff; sequential fwd X/YZ FFTs + combine + inverse
__global__ void __launch_bounds__(256, 5) k_specX() {
    extern __shared__ float2 tile[];            // 2 * K2TS float2 (18 KB)
    __shared__ float2 twf[64];
    __shared__ float2 twi[64];
    int tid = threadIdx.x, l = tid >> 5, t = tid & 31;
    build_tw64(twf, tid, -1.f);
    if (tid >= 64 && tid < 128) build_tw64(twi, tid - 64, 1.f);
    int c = blockIdx.x, kz = blockIdx.y, b = blockIdx.z;
    int kya0 = K2L*c;
    const float TWOPI = 6.28318530717958647f;
    float fz = (float)kz;
    float2* tileX  = tile;
    float2* tileYZ = tile + K2TS;
    // ---- load phase: only non-cut lines (ch0 raw; ch1,ch2 combined)
    {
        const float2* src0 = d_sp + ((size_t)(b*3 + 0)*NRES*NKZ + kz)*NRES + kya0;
        const float2* src1 = src0 + (size_t)NRES*NKZ*NRES;
        const float2* src2 = src1 + (size_t)NRES*NKZ*NRES;
        for (int i = tid; i < 128*K2L; i += 256) {
            int xx = i >> 3, kyl = i & 7;
            int kya = kya0 + kyl;
            int fyi = 4*bitrev5(kya & 31) + (kya >> 5);
            float fy = (fyi < 64) ? (float)fyi : (float)(fyi - 128);
            if (fy*fy + fz*fz > CUT2) continue;        // cut line: no load
            size_t off = (size_t)xx*NKZ*NRES + kyl;
            float2 e1 = src1[off];
            float2 e2 = src2[off];
            tileX[xx*K2P + kyl] = src0[off];
            tileYZ[xx*K2P + kyl] = make_float2(TWOPI*(fy*e1.x + fz*e2.x),
                                               TWOPI*(fy*e1.y + fz*e2.y));
        }
    }
    __syncthreads();
    int kya = kya0 + l;
    int fyi = 4*bitrev5(kya & 31) + (kya >> 5);
    float fy = (fyi < 64) ? (float)fyi : (float)(fyi - 128);
    int u = bitrev5(t);
    if (fy*fy + fz*fz > CUT2) {
        // cut line: output is ~0 -> zero this warp's column
        float2 z0 = make_float2(0.f, 0.f);
#pragma unroll
        for (int r = 0; r < 4; r++) tileX[(t + 32*r)*K2P + l] = z0;
    } else {
        // fwd FFT of X channel; park spectrum in own column
        {
            float2 vX[4];
#pragma unroll
            for (int r = 0; r < 4; r++) vX[r] = tileX[(t + 32*r)*K2P + l];
            warp_fft128<0>(vX, twf, t);
#pragma unroll
            for (int r = 0; r < 4; r++) tileX[(t + 32*r)*K2P + l] = vX[r];
        }
        // fwd FFT of YZ channel, then combine with parked X spectrum
        float2 v[4];
#pragma unroll
        for (int r = 0; r < 4; r++) v[r] = tileYZ[(t + 32*r)*K2P + l];
        warp_fft128<0>(v, twf, t);
#pragma unroll
        for (int r = 0; r < 4; r++) {
            float2 xs = tileX[(t + 32*r)*K2P + l];
            int kx = 4*u + r;
            float fx = (float)(kx < 64 ? kx : kx - 128);
            float wx = TWOPI * fx;
            float2 acc = make_float2(wx*xs.x + v[r].x, wx*xs.y + v[r].y);
            float d2 = fx*fx + fy*fy + fz*fz;
            float G = expf(-0.01220703125f * d2);            // 0.5*(sig*2/128)^2
            float L = -39.478417604357434f * d2 + 1e-6f;     // -4*pi^2*|f|^2 + eps
            v[r] = make_float2(G*acc.y/L, -G*acc.x/L);       // -i*G*acc/L
            if (kx == 0 && fyi == 0 && kz == 0) v[r] = make_float2(0.f, 0.f);
        }
        warp_ifft128_rev(v, twi, t);            // -> natural x order
#pragma unroll
        for (int r = 0; r < 4; r++) tileX[(t + 32*r)*K2P + l] = v[r];
    }
    __syncthreads();
    float2* dst = d_inv1 + (size_t)(b*NKZ + kz)*NRES*NRES + kya0;
    for (int i = tid; i < 128*K2L; i += 256) {
        int xx = i >> 3, kyl = i & 7;
        dst[(size_t)xx*NRES + kyl] = tileX[xx*K2P + kyl];
    }
}

// --------------- K3: inverse y-FFT (mirror-DIT) + packed-pair C2R z-FFTs
__global__ void __launch_bounds__(512, 3) k_invYZ() {
    extern __shared__ float2 sh[];              // 128*65 float2 : sh[y][kz]
    __shared__ float2 twi[64];
    int tid = threadIdx.x, w = tid >> 5, t = tid & 31;
    build_tw64(twi, tid, 1.f);
    __syncthreads();
    int x = blockIdx.x, b = blockIdx.y;
    // stage 1: ky-lines; kz >= KZCUT rows are identically zero (skip load+FFT)
    for (int kz = w; kz < NKZ; kz += 16) {
        if (kz < KZCUT) {
            const float2* in = d_inv1 + ((size_t)(b*NKZ + kz)*NRES + x)*NRES;
            float2 v[4];
#pragma unroll
            for (int r = 0; r < 4; r++) v[r] = in[t + 32*r];
            warp_ifft128_rev(v, twi, t);        // natural y = t+32r
#pragma unroll
            for (int r = 0; r < 4; r++) sh[(t + 32*r)*NKZ + kz] = v[r];
        } else {
            float2 z0 = make_float2(0.f, 0.f);
#pragma unroll
            for (int r = 0; r < 4; r++) sh[(t + 32*r)*NKZ + kz] = z0;
        }
    }
    __syncthreads();
    // stage 2: 64 packed C2R pairs: G = S_{2m} + i*S_{2m+1}, one inverse FFT
    const float sc = 1.0f / 2097152.0f;         // 1/128^3
    float* outb = d_phi + (size_t)(b*NRES + x) * NRES * NRES;
    for (int j = 0; j < 4; j++) {
        int m = w + 16*j;
        const float2* rowA = sh + (2*m)*NKZ;
        const float2* rowB = rowA + NKZ;
        float2 v[4];
#pragma unroll
        for (int r = 0; r < 4; r++) {
            int k = t + 32*r;
            if (k <= 64) {
                float2 A = rowA[k], B = rowB[k];
                v[r] = make_float2(A.x - B.y, A.y + B.x);
            } else {
                int k2 = 128 - k;
                float2 A = rowA[k2], B = rowB[k2];
                v[r] = make_float2(A.x + B.y, B.x - A.y);
            }
        }
        warp_fft128<1>(v, twi, t);
        float* oA = outb + (2*m)*NRES;
        float* oB = oA + NRES;
#pragma unroll
        for (int r = 0; r < 4; r++) {
            oA[t + 32*r] = v[r].x * sc;         // y=2m,   permuted z
            oB[t + 32*r] = v[r].y * sc;         // y=2m+1, permuted z
        }
    }
}

// ---------------------------------------------------------------- gather + mean
__global__ void k_gather(const float* __restrict__ V) {
    __shared__ float red[256];
    int id = blockIdx.x * 256 + threadIdx.x;    // 131072; b uniform per block
    int b = id >> 16;
    float px = V[3*id+0]*128.f, py = V[3*id+1]*128.f, pz = V[3*id+2]*128.f;
    int ix0 = max(0, min(127, (int)floorf(px)));
    int iy0 = max(0, min(127, (int)floorf(py)));
    int iz0 = max(0, min(127, (int)floorf(pz)));
    float fx = px - (float)ix0, fy = py - (float)iy0, fz = pz - (float)iz0;
    int ix[2] = {ix0, (ix0+1)&127};
    int iy[2] = {iy0, (iy0+1)&127};
    int az[2] = {paddr(iz0), paddr((iz0+1)&127)};
    float wx[2] = {1.f-fx, fx}, wy[2] = {1.f-fy, fy}, wz[2] = {1.f-fz, fz};
    const float* ph = d_phi + (size_t)b*VOL;
    float fv = 0.f;
#pragma unroll
    for (int cx = 0; cx < 2; cx++)
#pragma unroll
        for (int cy = 0; cy < 2; cy++)
#pragma unroll
            for (int cz = 0; cz < 2; cz++)
                fv += wx[cx]*wy[cy]*wz[cz] * ph[(ix[cx]*NRES + iy[cy])*NRES + az[cz]];
    red[threadIdx.x] = fv;
    __syncthreads();
    for (int s = 128; s > 0; s >>= 1) {
        if (threadIdx.x < s) red[threadIdx.x] += red[threadIdx.x + s];
        __syncthreads();
    }
    if (threadIdx.x == 0) atomicAdd(&d_accum[b], red[0]);
}

// ---------------------------------------------------------------- finalize
__global__ void k_final(float* __restrict__ out) {
    int id = blockIdx.x * 256 + threadIdx.x;    // 4194304 total
    int b = id >> 21;
    int z = id & 127;
    int base = id - z;
    float off  = d_accum[b] * (1.0f/65536.0f);
    float p000 = d_phi[(size_t)b * VOL];        // paddr(0)=0
    float s = 0.5f / fabsf(p000 - off);
    out[id] = -(d_phi[base + paddr(z)] - off) * s;
}

// ---------------------------------------------------------------- launch
extern "C" void kernel_launch(void* const* d_in, const int* in_sizes, int n_in,
                              void* d_out, int out_size) {
    const float* V = (const float*)d_in[0];
    const float* N = (const float*)d_in[1];
    float* out = (float*)d_out;

    const int k1Bytes = 64*K1PD*sizeof(float2);       // 66048
    const int k3Bytes = NRES*NKZ*sizeof(float2);      // 66560
    const int k2Bytes = 2*K2TS*sizeof(float2);        // 18432
    cudaFuncSetAttribute(k_fwdZY, cudaFuncAttributeMaxDynamicSharedMemorySize, k1Bytes);
    cudaFuncSetAttribute(k_invYZ, cudaFuncAttributeMaxDynamicSharedMemorySize, k3Bytes);

    k_zero<<<4096, 256>>>();
    k_scatter<<<512, 256>>>(V, N);
    k_fwdZY<<<dim3(128, 6), 512, k1Bytes>>>();        // 768 planes
    k_specX<<<dim3(16, 65, 2), 256, k2Bytes>>>();     // 2080 tiles of 8 lines
    k_invYZ<<<dim3(128, 2), 512, k3Bytes>>>();        // 256 planes
    k_gather<<<512, 256>>>(V);
    k_final<<<16384, 256>>>(out);
}